// round 1
// baseline (speedup 1.0000x reference)
#include <cuda_runtime.h>
#include <cuda_bf16.h>
#include <math.h>

// ---------------------------------------------------------------------------
// Problem constants
//   b=4, n=1024, hidden=769 (d=768), heads=12, head_dim=64, mlp=3072 (+1=3073)
// ---------------------------------------------------------------------------
#define BATCH 4
#define SEQ   1024
#define D     768
#define DH    769
#define HEADS 12
#define HDIM  64
#define BH    (BATCH*HEADS)      // 48
#define ROWS  (BATCH*SEQ)        // 4096
#define DM    3072
#define DMH   3073

// ---------------------------------------------------------------------------
// Scratch (static device globals; no allocation allowed)
// ---------------------------------------------------------------------------
__device__ float g_X1 [ROWS*DH];        // ln1(x) with time at col 0
__device__ float g_Qh [BH*SEQ*HDIM];    // Q per-head contiguous
__device__ float g_Kh [BH*SEQ*HDIM];
__device__ float g_Vh [BH*SEQ*HDIM];    // becomes v_tan after prep
__device__ float g_qt [BH*SEQ];
__device__ float g_kt [BH*SEQ];
__device__ float g_AIN[ROWS*DH];        // [t_new, attn_s] input to Wo
__device__ float g_Th [ROWS*HEADS];     // per-head time components
__device__ float g_MO [ROWS*D];         // Wo output
__device__ float g_OUT[ROWS*D];         // residual stream (spatial)
__device__ float g_H  [ROWS*DH];        // ln2 output with time
__device__ float g_H1 [ROWS*DMH];       // gelu mlp hidden with time
__device__ float g_G2 [ROWS*D];         // Wm2 output

// ---------------------------------------------------------------------------
// Reductions
// ---------------------------------------------------------------------------
__device__ __forceinline__ float warpSum(float v){
  #pragma unroll
  for(int o=16;o>0;o>>=1) v += __shfl_xor_sync(0xffffffffu, v, o);
  return v;
}
__device__ __forceinline__ float blockSum(float v, float* sh){
  int lane = threadIdx.x & 31, w = threadIdx.x >> 5;
  v = warpSum(v);
  if(lane==0) sh[w] = v;
  __syncthreads();
  float r = (threadIdx.x < 8) ? sh[threadIdx.x] : 0.f;
  if(w==0) r = warpSum(r);
  if(threadIdx.x==0) sh[0] = r;
  __syncthreads();
  r = sh[0];
  __syncthreads();
  return r;
}

// ---------------------------------------------------------------------------
// LayerNorm (+optional second input add, +optional raw-sum output) + add_time
//   out row layout: [t, s0..s767] (stride DH)
// ---------------------------------------------------------------------------
__global__ void ln_addtime_kernel(const float* __restrict__ in1, int ld1, int off1,
                                  const float* __restrict__ in2, int ld2, int off2,
                                  const float* __restrict__ gv, const float* __restrict__ bv,
                                  float* __restrict__ outp, float* __restrict__ rawOut)
{
  __shared__ float red[8];
  int row = blockIdx.x, tid = threadIdx.x;
  float v[3];
  #pragma unroll
  for(int q=0;q<3;q++){
    int j = tid + q*256;
    float x = in1[row*ld1 + off1 + j];
    if(in2) x += in2[row*ld2 + off2 + j];
    v[q] = x;
    if(rawOut) rawOut[row*D + j] = x;
  }
  float s  = v[0]+v[1]+v[2];
  float s2 = v[0]*v[0]+v[1]*v[1]+v[2]*v[2];
  s  = blockSum(s,  red);
  float mu = s * (1.f/768.f);
  s2 = blockSum(s2, red);
  float var = s2*(1.f/768.f) - mu*mu;
  float rstd = rsqrtf(var + 1e-5f);
  float w[3]; float n2 = 0.f;
  #pragma unroll
  for(int q=0;q<3;q++){
    int j = tid + q*256;
    w[q] = (v[q]-mu)*rstd*gv[j] + bv[j];
    n2 += w[q]*w[q];
  }
  n2 = blockSum(n2, red);
  #pragma unroll
  for(int q=0;q<3;q++){
    int j = tid + q*256;
    outp[row*DH + 1 + j] = w[q];
  }
  if(tid==0) outp[row*DH] = sqrtf(1.f + n2);
}

// ---------------------------------------------------------------------------
// SGEMM: C[M,N] = A[M,K] * B[N,K]^T   (both row-major)
//   128x128 tile, BK=8, 256 threads, 8x8 per thread.
//   act: 0 none, 1 exact gelu.   headScatter: write to per-head layout.
// ---------------------------------------------------------------------------
__global__ void sgemm_kernel(const float* __restrict__ A, const float* __restrict__ B,
                             float* __restrict__ C, int M, int Nn, int Kk,
                             int ldc, int act, int headScatter)
{
  __shared__ float As[8][128];
  __shared__ float Bs[8][128];
  int tid = threadIdx.x;
  int row0 = blockIdx.y*128, col0 = blockIdx.x*128;
  int tx = tid & 15, ty = tid >> 4;
  float acc[8][8];
  #pragma unroll
  for(int i=0;i<8;i++)
    #pragma unroll
    for(int j=0;j<8;j++) acc[i][j]=0.f;

  for(int k0=0;k0<Kk;k0+=8){
    #pragma unroll
    for(int q=0;q<4;q++){
      int e = tid*4 + q;
      int m = e >> 3, kk = e & 7;
      int k = k0 + kk;
      As[kk][m] = (k<Kk) ? A[(size_t)(row0+m)*Kk + k] : 0.f;
      Bs[kk][m] = (k<Kk) ? B[(size_t)(col0+m)*Kk + k] : 0.f;
    }
    __syncthreads();
    #pragma unroll
    for(int kk=0;kk<8;kk++){
      float a[8], b[8];
      #pragma unroll
      for(int i=0;i<8;i++) a[i]=As[kk][ty*8+i];
      #pragma unroll
      for(int j=0;j<8;j++) b[j]=Bs[kk][tx*8+j];
      #pragma unroll
      for(int i=0;i<8;i++)
        #pragma unroll
        for(int j=0;j<8;j++) acc[i][j] = fmaf(a[i], b[j], acc[i][j]);
    }
    __syncthreads();
  }
  #pragma unroll
  for(int i=0;i<8;i++){
    int r = row0 + ty*8 + i;
    #pragma unroll
    for(int j=0;j<8;j++){
      int c = col0 + tx*8 + j;
      float v = acc[i][j];
      if(act==1) v = 0.5f*v*(1.f + erff(v*0.70710678118654752f));
      if(headScatter){
        int b_ = r >> 10, ii = r & 1023;
        int h = c >> 6, cc = c & 63;
        C[(size_t)(((b_*HEADS+h)<<10) + ii)*HDIM + cc] = v;
      } else {
        C[(size_t)r*ldc + c] = v;
      }
    }
  }
}

// ---------------------------------------------------------------------------
// Prep: q_t, k_t, and v -> v_tan (logmap0 spatial) in place.  One warp/row.
// ---------------------------------------------------------------------------
__global__ void prep_kernel()
{
  int w = blockIdx.x*8 + (threadIdx.x>>5);
  int lane = threadIdx.x & 31;
  const float* q = g_Qh + (size_t)w*HDIM;
  float s = 0.f;
  #pragma unroll
  for(int e=0;e<2;e++){ float x = q[lane+32*e]; s += x*x; }
  s = warpSum(s);
  if(lane==0) g_qt[w] = sqrtf(1.f + s);

  const float* k = g_Kh + (size_t)w*HDIM;
  s = 0.f;
  #pragma unroll
  for(int e=0;e<2;e++){ float x = k[lane+32*e]; s += x*x; }
  s = warpSum(s);
  if(lane==0) g_kt[w] = sqrtf(1.f + s);

  float* v = g_Vh + (size_t)w*HDIM;
  float vv[2];
  s = 0.f;
  #pragma unroll
  for(int e=0;e<2;e++){ vv[e] = v[lane+32*e]; s += vv[e]*vv[e]; }
  s = warpSum(s);
  float sn = sqrtf(s);
  float vt = sqrtf(1.f + s);
  float vc = fmaxf(vt, 1.0000001f);
  float dist = __logf(vc + sqrtf((vc-1.f)*(vc+1.f)));
  float scl = dist / fmaxf(sn, 1e-8f);
  #pragma unroll
  for(int e=0;e<2;e++) v[lane+32*e] = vv[e]*scl;
}

// ---------------------------------------------------------------------------
// Fused hyperbolic attention (flash-style). 64x64 tiles, 256 threads (16x16).
// ---------------------------------------------------------------------------
#define ATT_SMEM_FLOATS (64*68*3 + 64*64 + 64)
__global__ void attn_kernel(const float* __restrict__ alpha_raw,
                            const float* __restrict__ tau_raw,
                            const float* __restrict__ lambda_raw)
{
  extern __shared__ float sm[];
  float* Qs  = sm;              // [64 d][68] (r index)
  float* Ks  = Qs + 64*68;      // [64 d][68] (c index)
  float* Vs  = Ks + 64*68;      // [64 j][64 c]
  float* Ps  = Vs + 64*64;      // [64 r][68]
  float* kts = Ps + 64*68;      // [64]

  int bh = blockIdx.y, it = blockIdx.x;
  int tid = threadIdx.x;
  int tx = tid & 15, ty = tid >> 4;

  const float* Qg    = g_Qh + ((size_t)bh*SEQ + it*64)*HDIM;
  const float* Kbase = g_Kh + (size_t)bh*SEQ*HDIM;
  const float* Vbase = g_Vh + (size_t)bh*SEQ*HDIM;
  const float* qtg   = g_qt + bh*SEQ + it*64;
  const float* ktg   = g_kt + bh*SEQ;

  float alpha = log1pf(expf(alpha_raw[0]));
  float tau   = log1pf(expf(tau_raw[0]));
  float lam   = log1pf(expf(lambda_raw[0]));
  const float sp_m = log1pf(expf(-0.1f));

  // load Q tile transposed
  {
    int j = tid >> 2, f4 = tid & 3;
    #pragma unroll
    for(int itn=0; itn<4; itn++){
      int d0 = f4*4 + itn*16;
      float4 v = *(const float4*)(Qg + j*HDIM + d0);
      Qs[(d0+0)*68+j]=v.x; Qs[(d0+1)*68+j]=v.y;
      Qs[(d0+2)*68+j]=v.z; Qs[(d0+3)*68+j]=v.w;
    }
  }
  // per-row scalars
  float qtv[4], coshOQ[4], shOQ[4], Bq[4];
  float mrow[4], lrow[4], accO[4][4];
  #pragma unroll
  for(int i=0;i<4;i++){
    float qt = qtg[4*ty+i];
    qtv[i] = qt;
    float cq = fmaxf(qt, 1.0000001f);
    float ct = __logf(cq + sqrtf((cq-1.f)*(cq+1.f)));
    ct = fminf(ct, 40.f);
    coshOQ[i] = cq;
    shOQ[i]   = sinhf(ct);
    Bq[i]     = alpha*ct/(1.f + alpha*ct);
    mrow[i] = -1e30f; lrow[i] = 0.f;
    #pragma unroll
    for(int c=0;c<4;c++) accO[i][c]=0.f;
  }

  for(int jt=0; jt<16; jt++){
    __syncthreads();
    // load K tile transposed + V tile direct + k_t
    {
      int j = tid >> 2, f4 = tid & 3;
      const float* Kg = Kbase + (size_t)(jt*64 + j)*HDIM;
      #pragma unroll
      for(int itn=0; itn<4; itn++){
        int d0 = f4*4 + itn*16;
        float4 v = *(const float4*)(Kg + d0);
        Ks[(d0+0)*68+j]=v.x; Ks[(d0+1)*68+j]=v.y;
        Ks[(d0+2)*68+j]=v.z; Ks[(d0+3)*68+j]=v.w;
      }
      #pragma unroll
      for(int itn=0; itn<4; itn++){
        int e = tid + itn*256;
        int r = e >> 4, c4 = (e & 15)*4;
        *(float4*)(Vs + r*64 + c4) = *(const float4*)(Vbase + (size_t)(jt*64+r)*HDIM + c4);
      }
      if(tid < 64) kts[tid] = ktg[jt*64 + tid];
    }
    __syncthreads();

    // S = Q . K^T
    float s[4][4];
    #pragma unroll
    for(int i=0;i<4;i++)
      #pragma unroll
      for(int j=0;j<4;j++) s[i][j]=0.f;
    #pragma unroll 16
    for(int d=0; d<64; d++){
      float a[4], b[4];
      *(float4*)a = *(const float4*)(Qs + d*68 + 4*ty);
      *(float4*)b = *(const float4*)(Ks + d*68 + 4*tx);
      #pragma unroll
      for(int i=0;i<4;i++)
        #pragma unroll
        for(int j=0;j<4;j++) s[i][j] = fmaf(a[i], b[j], s[i][j]);
    }

    float ktv[4], ckv[4];
    #pragma unroll
    for(int j=0;j<4;j++){
      ktv[j] = kts[4*tx+j];
      ckv[j] = fmaxf(ktv[j], 1.0000001f);
    }

    // logits
    float z[4][4];
    #pragma unroll
    for(int i=0;i<4;i++){
      #pragma unroll
      for(int j=0;j<4;j++){
        float rawc = fmaxf(qtv[i]*ktv[j] - s[i][j], 1.0f);
        bool selfp = rawc < 1.00001f;
        float c  = selfp ? 2.f : rawc;
        float sh = sqrtf((c-1.f)*(c+1.f));     // sinh(arccosh(c))
        float dist = __logf(c + sh);           // arccosh(c)
        float Z = (rawc*coshOQ[i] - ckv[j]) / (shOQ[i]*sh);
        Z = selfp ? 1.f : fminf(fmaxf(Z,-1.f),1.f);
        float dl = fminf(dist, 40.f);
        float pen = -lam*__logf(1.f + dl*dl);
        float ent = __logf(1.f + __expf(Bq[i] + Z - 0.1f)) - sp_m;
        z[i][j] = pen - tau*ent;
      }
    }

    // online softmax + write P
    #pragma unroll
    for(int i=0;i<4;i++){
      float mx = fmaxf(fmaxf(z[i][0],z[i][1]), fmaxf(z[i][2],z[i][3]));
      #pragma unroll
      for(int o=1;o<16;o<<=1) mx = fmaxf(mx, __shfl_xor_sync(0xffffffffu, mx, o));
      float mnew = fmaxf(mrow[i], mx);
      float sc = __expf(mrow[i] - mnew);
      float p[4], ps = 0.f;
      #pragma unroll
      for(int j=0;j<4;j++){ p[j] = __expf(z[i][j]-mnew); ps += p[j]; }
      #pragma unroll
      for(int o=1;o<16;o<<=1) ps += __shfl_xor_sync(0xffffffffu, ps, o);
      lrow[i] = lrow[i]*sc + ps;
      mrow[i] = mnew;
      #pragma unroll
      for(int c=0;c<4;c++) accO[i][c] *= sc;
      *(float4*)(Ps + (4*ty+i)*68 + 4*tx) = make_float4(p[0],p[1],p[2],p[3]);
    }
    __syncthreads();

    // O += P @ Vtan
    #pragma unroll 8
    for(int j=0;j<64;j++){
      float vv[4];
      *(float4*)vv = *(const float4*)(Vs + j*64 + 4*tx);
      #pragma unroll
      for(int i=0;i<4;i++){
        float pp = Ps[(4*ty+i)*68 + j];
        #pragma unroll
        for(int c=0;c<4;c++) accO[i][c] = fmaf(pp, vv[c], accO[i][c]);
      }
    }
  }

  // epilogue: normalize, expmap0, write per-head output
  int b_ = bh / HEADS, h = bh % HEADS;
  #pragma unroll
  for(int i=0;i<4;i++){
    float inv = 1.f/(lrow[i]*(1.f + 1e-8f));
    float ag[4]; float nn = 0.f;
    #pragma unroll
    for(int c=0;c<4;c++){ ag[c] = accO[i][c]*inv; nn += ag[c]*ag[c]; }
    #pragma unroll
    for(int o=1;o<16;o<<=1) nn += __shfl_xor_sync(0xffffffffu, nn, o);
    nn = sqrtf(nn);
    float t   = coshf(nn);
    float scl = sinhf(nn)/fmaxf(nn, 1e-8f);
    int grow = b_*SEQ + it*64 + 4*ty + i;
    #pragma unroll
    for(int c=0;c<4;c++)
      g_AIN[(size_t)grow*DH + 1 + h*HDIM + 4*tx + c] = ag[c]*scl;
    if(tx==0) g_Th[grow*HEADS + h] = t;
  }
}

// t_new = sqrt(sum_h t_h^2 - (H-1)*K)
__global__ void tnew_kernel()
{
  int r = blockIdx.x*256 + threadIdx.x;
  if(r >= ROWS) return;
  float s = 0.f;
  #pragma unroll
  for(int h=0; h<HEADS; h++){ float t = g_Th[r*HEADS+h]; s += t*t; }
  g_AIN[(size_t)r*DH] = sqrtf(s - (float)(HEADS-1));
}

// time for mlp hidden: g_H1[row*DMH] = sqrt(1 + sum_{3072} g1^2)
__global__ void time_mlp_kernel()
{
  __shared__ float red[8];
  int row = blockIdx.x, tid = threadIdx.x;
  float s = 0.f;
  #pragma unroll
  for(int q=0;q<12;q++){
    float x = g_H1[(size_t)row*DMH + 1 + tid + q*256];
    s += x*x;
  }
  s = blockSum(s, red);
  if(tid==0) g_H1[(size_t)row*DMH] = sqrtf(1.f + s);
}

// final: res = G2 + OUT; d_out = [sqrt(1+|res|^2), res]
__global__ void final_kernel(float* __restrict__ out)
{
  __shared__ float red[8];
  int row = blockIdx.x, tid = threadIdx.x;
  float v[3]; float s = 0.f;
  #pragma unroll
  for(int q=0;q<3;q++){
    int j = tid + q*256;
    float x = g_G2[(size_t)row*D + j] + g_OUT[(size_t)row*D + j];
    v[q] = x; s += x*x;
  }
  s = blockSum(s, red);
  #pragma unroll
  for(int q=0;q<3;q++){
    int j = tid + q*256;
    out[(size_t)row*DH + 1 + j] = v[q];
  }
  if(tid==0) out[(size_t)row*DH] = sqrtf(1.f + s);
}

// ---------------------------------------------------------------------------
// Launch
// ---------------------------------------------------------------------------
extern "C" void kernel_launch(void* const* d_in, const int* in_sizes, int n_in,
                              void* d_out, int out_size)
{
  const float* x    = (const float*)d_in[0];
  const float* Wq   = (const float*)d_in[1];
  const float* Wk   = (const float*)d_in[2];
  const float* Wv   = (const float*)d_in[3];
  const float* Wo   = (const float*)d_in[4];
  const float* ln1g = (const float*)d_in[5];
  const float* ln1b = (const float*)d_in[6];
  const float* ln2g = (const float*)d_in[7];
  const float* ln2b = (const float*)d_in[8];
  const float* Wm1  = (const float*)d_in[9];
  const float* Wm2  = (const float*)d_in[10];
  const float* araw = (const float*)d_in[11];
  const float* traw = (const float*)d_in[12];
  const float* lraw = (const float*)d_in[13];
  float* out = (float*)d_out;

  float *pX1, *pQh, *pKh, *pVh, *pAIN, *pMO, *pH, *pH1, *pG2;
  cudaGetSymbolAddress((void**)&pX1,  g_X1);
  cudaGetSymbolAddress((void**)&pQh,  g_Qh);
  cudaGetSymbolAddress((void**)&pKh,  g_Kh);
  cudaGetSymbolAddress((void**)&pVh,  g_Vh);
  cudaGetSymbolAddress((void**)&pAIN, g_AIN);
  cudaGetSymbolAddress((void**)&pMO,  g_MO);
  cudaGetSymbolAddress((void**)&pH,   g_H);
  cudaGetSymbolAddress((void**)&pH1,  g_H1);
  cudaGetSymbolAddress((void**)&pG2,  g_G2);

  cudaFuncSetAttribute(attn_kernel, cudaFuncAttributeMaxDynamicSharedMemorySize,
                       ATT_SMEM_FLOATS*sizeof(float));

  // 1. ln1 + add_time
  ln_addtime_kernel<<<ROWS,256>>>(x, DH, 1, nullptr, 0, 0, ln1g, ln1b, pX1, nullptr);

  // 2. QKV projections -> per-head layout
  dim3 g768(D/128, ROWS/128);
  sgemm_kernel<<<g768,256>>>(pX1, Wq, pQh, ROWS, D, DH, 0, 0, 1);
  sgemm_kernel<<<g768,256>>>(pX1, Wk, pKh, ROWS, D, DH, 0, 0, 1);
  sgemm_kernel<<<g768,256>>>(pX1, Wv, pVh, ROWS, D, DH, 0, 0, 1);

  // 3. q_t, k_t, v_tan
  prep_kernel<<<(BH*SEQ)/8, 256>>>();

  // 4. fused hyperbolic attention
  attn_kernel<<<dim3(SEQ/64, BH), 256, ATT_SMEM_FLOATS*sizeof(float)>>>(araw, traw, lraw);

  // 5. t_new
  tnew_kernel<<<ROWS/256, 256>>>();

  // 6. Wo projection
  sgemm_kernel<<<g768,256>>>(pAIN, Wo, pMO, ROWS, D, DH, D, 0, 0);

  // 7. residual + ln2 + add_time (also stash residual stream)
  ln_addtime_kernel<<<ROWS,256>>>(pMO, D, 0, x, DH, 1, ln2g, ln2b, pH, (float*)nullptr);
  // need rawOut=g_OUT: relaunch properly below (single call with rawOut)
  // (handled in the call above? no — do it correctly:)

  // NOTE: the call above omitted rawOut; issue the correct one instead.
  // To keep determinism we overwrite with the correct computation:
  {
    float* pOUT; cudaGetSymbolAddress((void**)&pOUT, g_OUT);
    ln_addtime_kernel<<<ROWS,256>>>(pMO, D, 0, x, DH, 1, ln2g, ln2b, pH, pOUT);
  }

  // 8. MLP up-projection with exact gelu, written into H1 spatial slots
  dim3 g3072(DM/128, ROWS/128);
  sgemm_kernel<<<g3072,256>>>(pH, Wm1, pH1 + 1, ROWS, DM, DH, DMH, 1, 0);

  // 9. time component of mlp hidden
  time_mlp_kernel<<<ROWS,256>>>();

  // 10. MLP down-projection
  sgemm_kernel<<<g768,256>>>(pH1, Wm2, pG2, ROWS, D, DMH, D, 0, 0);

  // 11. final residual + add_time -> output
  final_kernel<<<ROWS,256>>>(out);
}

// round 3
// speedup vs baseline: 2.0699x; 2.0699x over previous
#include <cuda_runtime.h>
#include <cuda_bf16.h>
#include <math.h>
#include <cstdint>

// ---------------------------------------------------------------------------
// Problem constants
// ---------------------------------------------------------------------------
#define BATCH 4
#define SEQ   1024
#define D     768
#define DH    769
#define HEADS 12
#define HDIM  64
#define BH    (BATCH*HEADS)      // 48
#define ROWS  (BATCH*SEQ)        // 4096
#define DM    3072
#define DMH   3073
#define KP1   800                // DH padded to mult of 32
#define KP2   3104               // DMH padded to mult of 32

// ---------------------------------------------------------------------------
// Scratch (static device globals; zero-initialized => pad columns stay zero)
// ---------------------------------------------------------------------------
__device__ float g_Qh [BH*SEQ*HDIM];
__device__ float g_Kh [BH*SEQ*HDIM];
__device__ float g_Vh [BH*SEQ*HDIM];
__device__ float g_qt [BH*SEQ];
__device__ float g_kt [BH*SEQ];
__device__ float g_Th [ROWS*HEADS];
__device__ float g_MO [ROWS*D];
__device__ float g_OUT[ROWS*D];
__device__ float g_G2 [ROWS*D];

// split-bf16 activation planes
__device__ __nv_bfloat16 g_X1h [ROWS*KP1], g_X1l [ROWS*KP1];
__device__ __nv_bfloat16 g_AINh[ROWS*KP1], g_AINl[ROWS*KP1];
__device__ __nv_bfloat16 g_Hh  [ROWS*KP1], g_Hl  [ROWS*KP1];
__device__ __nv_bfloat16 g_H1h [ROWS*KP2], g_H1l [ROWS*KP2];

// split-bf16 weight planes (padded K stride)
__device__ __nv_bfloat16 g_Wqh[D*KP1],  g_Wql[D*KP1];
__device__ __nv_bfloat16 g_Wkh[D*KP1],  g_Wkl[D*KP1];
__device__ __nv_bfloat16 g_Wvh[D*KP1],  g_Wvl[D*KP1];
__device__ __nv_bfloat16 g_Woh[D*KP1],  g_Wol[D*KP1];
__device__ __nv_bfloat16 g_W1h[DM*KP1], g_W1l[DM*KP1];
__device__ __nv_bfloat16 g_W2h[D*KP2],  g_W2l[D*KP2];

// ---------------------------------------------------------------------------
// Helpers
// ---------------------------------------------------------------------------
__device__ __forceinline__ float warpSum(float v){
  #pragma unroll
  for(int o=16;o>0;o>>=1) v += __shfl_xor_sync(0xffffffffu, v, o);
  return v;
}
__device__ __forceinline__ float blockSum(float v, float* sh){
  int lane = threadIdx.x & 31, w = threadIdx.x >> 5;
  v = warpSum(v);
  if(lane==0) sh[w] = v;
  __syncthreads();
  float r = (threadIdx.x < 8) ? sh[threadIdx.x] : 0.f;
  if(w==0) r = warpSum(r);
  if(threadIdx.x==0) sh[0] = r;
  __syncthreads();
  r = sh[0];
  __syncthreads();
  return r;
}
__device__ __forceinline__ void splitStore(__nv_bfloat16* ph, __nv_bfloat16* pl, float x){
  __nv_bfloat16 h = __float2bfloat16(x);
  *ph = h;
  *pl = __float2bfloat16(x - __bfloat162float(h));
}
__device__ __forceinline__ void cpasync16(void* s, const void* g){
  unsigned int sa = (unsigned int)__cvta_generic_to_shared(s);
  asm volatile("cp.async.cg.shared.global [%0], [%1], 16;\n" :: "r"(sa), "l"(g));
}
#define CP_COMMIT asm volatile("cp.async.commit_group;\n")
#define CP_WAIT(n) asm volatile("cp.async.wait_group %0;\n" :: "n"(n))

__device__ __forceinline__ void mma16816(float* d, const unsigned* a, const unsigned* b){
  asm volatile("mma.sync.aligned.m16n8k16.row.col.f32.bf16.bf16.f32 "
    "{%0,%1,%2,%3},{%4,%5,%6,%7},{%8,%9},{%0,%1,%2,%3};"
    : "+f"(d[0]),"+f"(d[1]),"+f"(d[2]),"+f"(d[3])
    : "r"(a[0]),"r"(a[1]),"r"(a[2]),"r"(a[3]),"r"(b[0]),"r"(b[1]));
}

// ---------------------------------------------------------------------------
// Weight split-convert:  W[N,K] fp32 -> Wh/Wl [N,KPp] bf16
// ---------------------------------------------------------------------------
__global__ void convsplit_kernel(const float* __restrict__ W,
                                 __nv_bfloat16* __restrict__ Wh,
                                 __nv_bfloat16* __restrict__ Wl,
                                 int Kk, int KPp, int total)
{
  int i = blockIdx.x*256 + threadIdx.x;
  if(i >= total) return;
  int r = i / Kk, c = i - r*Kk;
  float x = W[i];
  __nv_bfloat16 h = __float2bfloat16(x);
  Wh[(size_t)r*KPp + c] = h;
  Wl[(size_t)r*KPp + c] = __float2bfloat16(x - __bfloat162float(h));
}

// ---------------------------------------------------------------------------
// LayerNorm (+optional add) + add_time, writes split-bf16 planes (stride KP1)
// ---------------------------------------------------------------------------
__global__ void ln_addtime_kernel(const float* __restrict__ in1, int ld1, int off1,
                                  const float* __restrict__ in2, int ld2, int off2,
                                  const float* __restrict__ gv, const float* __restrict__ bv,
                                  __nv_bfloat16* __restrict__ outh,
                                  __nv_bfloat16* __restrict__ outl,
                                  float* __restrict__ rawOut)
{
  __shared__ float red[8];
  int row = blockIdx.x, tid = threadIdx.x;
  float v[3];
  #pragma unroll
  for(int q=0;q<3;q++){
    int j = tid + q*256;
    float x = in1[(size_t)row*ld1 + off1 + j];
    if(in2) x += in2[(size_t)row*ld2 + off2 + j];
    v[q] = x;
    if(rawOut) rawOut[(size_t)row*D + j] = x;
  }
  float s  = v[0]+v[1]+v[2];
  float s2 = v[0]*v[0]+v[1]*v[1]+v[2]*v[2];
  s  = blockSum(s,  red);
  float mu = s * (1.f/768.f);
  s2 = blockSum(s2, red);
  float var = s2*(1.f/768.f) - mu*mu;
  float rstd = rsqrtf(var + 1e-5f);
  float w[3]; float n2 = 0.f;
  #pragma unroll
  for(int q=0;q<3;q++){
    int j = tid + q*256;
    w[q] = (v[q]-mu)*rstd*gv[j] + bv[j];
    n2 += w[q]*w[q];
  }
  n2 = blockSum(n2, red);
  #pragma unroll
  for(int q=0;q<3;q++){
    int j = tid + q*256;
    splitStore(outh + (size_t)row*KP1 + 1 + j, outl + (size_t)row*KP1 + 1 + j, w[q]);
  }
  if(tid==0) splitStore(outh + (size_t)row*KP1, outl + (size_t)row*KP1, sqrtf(1.f + n2));
}

// ---------------------------------------------------------------------------
// Tensor-core split-bf16 GEMM: C[M,N] = A[M,K]*B[N,K]^T
//   128x128 CTA tile, BK=32, 8 warps (2x4), 64x32 warp tile, cp.async x2 stages
//   mode 0: fp32 out (ldc);  1: fp32 head-scatter;  2: gelu + split-bf16 out
// ---------------------------------------------------------------------------
#define HG_STAGE_BF16 (4*128*40)          // 20480 bf16 per stage
#define HG_SMEM_BYTES (2*HG_STAGE_BF16*2) // 81920 bytes

__global__ void __launch_bounds__(256,1) hgemm_kernel(
    const __nv_bfloat16* __restrict__ Ah, const __nv_bfloat16* __restrict__ Al,
    const __nv_bfloat16* __restrict__ Bh, const __nv_bfloat16* __restrict__ Bl,
    float* __restrict__ Cf, __nv_bfloat16* __restrict__ Ch, __nv_bfloat16* __restrict__ Cl,
    int KP, int ldc, int mode)
{
  extern __shared__ __nv_bfloat16 smb[];
  int tid = threadIdx.x;
  int lane = tid & 31, wid = tid >> 5;
  int wm = wid >> 2, wn = wid & 3;
  int g = lane >> 2, t = lane & 3;
  int row0 = blockIdx.y*128, col0 = blockIdx.x*128;

  float acc[4][4][4];
  #pragma unroll
  for(int mi=0;mi<4;mi++)
    #pragma unroll
    for(int ni=0;ni<4;ni++)
      #pragma unroll
      for(int e=0;e<4;e++) acc[mi][ni][e]=0.f;

  const int niter = KP >> 5;

  // ---- prologue: load tile 0 ----
  {
    __nv_bfloat16* s = smb;
    #pragma unroll
    for(int q=0;q<2;q++){
      int ch = tid + q*256;
      int row = ch>>2, cc = (ch&3)*8;
      cpasync16(s +             row*40 + cc, Ah + (size_t)(row0+row)*KP + cc);
      cpasync16(s +  5120 +     row*40 + cc, Al + (size_t)(row0+row)*KP + cc);
      cpasync16(s + 10240 +     row*40 + cc, Bh + (size_t)(col0+row)*KP + cc);
      cpasync16(s + 15360 +     row*40 + cc, Bl + (size_t)(col0+row)*KP + cc);
    }
    CP_COMMIT;
  }

  for(int it=0; it<niter; it++){
    if(it+1 < niter){
      int k0 = (it+1) << 5;
      __nv_bfloat16* s = smb + ((it+1)&1)*HG_STAGE_BF16;
      #pragma unroll
      for(int q=0;q<2;q++){
        int ch = tid + q*256;
        int row = ch>>2, cc = (ch&3)*8;
        cpasync16(s +             row*40 + cc, Ah + (size_t)(row0+row)*KP + k0 + cc);
        cpasync16(s +  5120 +     row*40 + cc, Al + (size_t)(row0+row)*KP + k0 + cc);
        cpasync16(s + 10240 +     row*40 + cc, Bh + (size_t)(col0+row)*KP + k0 + cc);
        cpasync16(s + 15360 +     row*40 + cc, Bl + (size_t)(col0+row)*KP + k0 + cc);
      }
      CP_COMMIT;
      CP_WAIT(1);
    } else {
      CP_WAIT(0);
    }
    __syncthreads();

    const unsigned* pAh = (const unsigned*)(smb + (it&1)*HG_STAGE_BF16);
    const unsigned* pAl = pAh + 2560;
    const unsigned* pBh = pAh + 5120;
    const unsigned* pBl = pAh + 7680;

    #pragma unroll
    for(int ks=0;ks<2;ks++){
      unsigned a_h[4][4], a_l[4][4], b_h[4][2], b_l[4][2];
      #pragma unroll
      for(int mi=0;mi<4;mi++){
        int base = (wm*64 + mi*16 + g)*20 + ks*8 + t;
        a_h[mi][0]=pAh[base];     a_h[mi][1]=pAh[base+160];
        a_h[mi][2]=pAh[base+4];   a_h[mi][3]=pAh[base+164];
        a_l[mi][0]=pAl[base];     a_l[mi][1]=pAl[base+160];
        a_l[mi][2]=pAl[base+4];   a_l[mi][3]=pAl[base+164];
      }
      #pragma unroll
      for(int ni=0;ni<4;ni++){
        int base = (wn*32 + ni*8 + g)*20 + ks*8 + t;
        b_h[ni][0]=pBh[base];  b_h[ni][1]=pBh[base+4];
        b_l[ni][0]=pBl[base];  b_l[ni][1]=pBl[base+4];
      }
      #pragma unroll
      for(int mi=0;mi<4;mi++)
        #pragma unroll
        for(int ni=0;ni<4;ni++) mma16816(acc[mi][ni], a_h[mi], b_h[ni]);
      #pragma unroll
      for(int mi=0;mi<4;mi++)
        #pragma unroll
        for(int ni=0;ni<4;ni++) mma16816(acc[mi][ni], a_h[mi], b_l[ni]);
      #pragma unroll
      for(int mi=0;mi<4;mi++)
        #pragma unroll
        for(int ni=0;ni<4;ni++) mma16816(acc[mi][ni], a_l[mi], b_h[ni]);
    }
    __syncthreads();
  }

  // ---- epilogue ----
  #pragma unroll
  for(int mi=0;mi<4;mi++){
    int rb = row0 + wm*64 + mi*16 + g;
    #pragma unroll
    for(int ni=0;ni<4;ni++){
      int cb = col0 + wn*32 + ni*8 + 2*t;
      float* a = acc[mi][ni];
      #pragma unroll
      for(int e=0;e<4;e++){
        int r = rb + (e>=2 ? 8 : 0);
        int c = cb + (e&1);
        float v = a[e];
        if(mode==2){
          v = 0.5f*v*(1.f + erff(v*0.70710678118654752f));
          splitStore(Ch + (size_t)r*ldc + c, Cl + (size_t)r*ldc + c, v);
        } else if(mode==1){
          int b_ = r >> 10, ii = r & 1023;
          int h = c >> 6, cc2 = c & 63;
          Cf[(size_t)(((b_*HEADS+h)<<10) + ii)*HDIM + cc2] = v;
        } else {
          Cf[(size_t)r*ldc + c] = v;
        }
      }
    }
  }
}

// ---------------------------------------------------------------------------
// Prep: q_t, k_t, v -> v_tan in place. One warp per (bh,row).
// ---------------------------------------------------------------------------
__global__ void prep_kernel()
{
  int w = blockIdx.x*8 + (threadIdx.x>>5);
  int lane = threadIdx.x & 31;
  const float* q = g_Qh + (size_t)w*HDIM;
  float s = 0.f;
  #pragma unroll
  for(int e=0;e<2;e++){ float x = q[lane+32*e]; s += x*x; }
  s = warpSum(s);
  if(lane==0) g_qt[w] = sqrtf(1.f + s);

  const float* k = g_Kh + (size_t)w*HDIM;
  s = 0.f;
  #pragma unroll
  for(int e=0;e<2;e++){ float x = k[lane+32*e]; s += x*x; }
  s = warpSum(s);
  if(lane==0) g_kt[w] = sqrtf(1.f + s);

  float* v = g_Vh + (size_t)w*HDIM;
  float vv[2];
  s = 0.f;
  #pragma unroll
  for(int e=0;e<2;e++){ vv[e] = v[lane+32*e]; s += vv[e]*vv[e]; }
  s = warpSum(s);
  float sn = sqrtf(s);
  float vt = sqrtf(1.f + s);
  float vc = fmaxf(vt, 1.0000001f);
  float dist = __logf(vc + sqrtf((vc-1.f)*(vc+1.f)));
  float scl = dist / fmaxf(sn, 1e-8f);
  #pragma unroll
  for(int e=0;e<2;e++) v[lane+32*e] = vv[e]*scl;
}

// ---------------------------------------------------------------------------
// Fused hyperbolic attention (flash-style). 64x64 tiles, 256 threads (16x16).
// Epilogue writes split-bf16 planes of AIN.
// ---------------------------------------------------------------------------
#define ATT_SMEM_FLOATS (64*68*3 + 64*64 + 64)
__global__ void attn_kernel(const float* __restrict__ alpha_raw,
                            const float* __restrict__ tau_raw,
                            const float* __restrict__ lambda_raw)
{
  extern __shared__ float sm[];
  float* Qs  = sm;
  float* Ks  = Qs + 64*68;
  float* Vs  = Ks + 64*68;
  float* Ps  = Vs + 64*64;
  float* kts = Ps + 64*68;

  int bh = blockIdx.y, it = blockIdx.x;
  int tid = threadIdx.x;
  int tx = tid & 15, ty = tid >> 4;

  const float* Qg    = g_Qh + ((size_t)bh*SEQ + it*64)*HDIM;
  const float* Kbase = g_Kh + (size_t)bh*SEQ*HDIM;
  const float* Vbase = g_Vh + (size_t)bh*SEQ*HDIM;
  const float* qtg   = g_qt + bh*SEQ + it*64;
  const float* ktg   = g_kt + bh*SEQ;

  float alpha = log1pf(expf(alpha_raw[0]));
  float tau   = log1pf(expf(tau_raw[0]));
  float lam   = log1pf(expf(lambda_raw[0]));
  const float sp_m = log1pf(expf(-0.1f));

  {
    int j = tid >> 2, f4 = tid & 3;
    #pragma unroll
    for(int itn=0; itn<4; itn++){
      int d0 = f4*4 + itn*16;
      float4 v = *(const float4*)(Qg + j*HDIM + d0);
      Qs[(d0+0)*68+j]=v.x; Qs[(d0+1)*68+j]=v.y;
      Qs[(d0+2)*68+j]=v.z; Qs[(d0+3)*68+j]=v.w;
    }
  }
  float qtv[4], coshOQ[4], shOQ[4], Bq[4];
  float mrow[4], lrow[4], accO[4][4];
  #pragma unroll
  for(int i=0;i<4;i++){
    float qt = qtg[4*ty+i];
    qtv[i] = qt;
    float cq = fmaxf(qt, 1.0000001f);
    float ct = __logf(cq + sqrtf((cq-1.f)*(cq+1.f)));
    ct = fminf(ct, 40.f);
    coshOQ[i] = cq;
    shOQ[i]   = sinhf(ct);
    Bq[i]     = alpha*ct/(1.f + alpha*ct);
    mrow[i] = -1e30f; lrow[i] = 0.f;
    #pragma unroll
    for(int c=0;c<4;c++) accO[i][c]=0.f;
  }

  for(int jt=0; jt<16; jt++){
    __syncthreads();
    {
      int j = tid >> 2, f4 = tid & 3;
      const float* Kg = Kbase + (size_t)(jt*64 + j)*HDIM;
      #pragma unroll
      for(int itn=0; itn<4; itn++){
        int d0 = f4*4 + itn*16;
        float4 v = *(const float4*)(Kg + d0);
        Ks[(d0+0)*68+j]=v.x; Ks[(d0+1)*68+j]=v.y;
        Ks[(d0+2)*68+j]=v.z; Ks[(d0+3)*68+j]=v.w;
      }
      #pragma unroll
      for(int itn=0; itn<4; itn++){
        int e = tid + itn*256;
        int r = e >> 4, c4 = (e & 15)*4;
        *(float4*)(Vs + r*64 + c4) = *(const float4*)(Vbase + (size_t)(jt*64+r)*HDIM + c4);
      }
      if(tid < 64) kts[tid] = ktg[jt*64 + tid];
    }
    __syncthreads();

    float s[4][4];
    #pragma unroll
    for(int i=0;i<4;i++)
      #pragma unroll
      for(int j=0;j<4;j++) s[i][j]=0.f;
    #pragma unroll 16
    for(int d=0; d<64; d++){
      float a[4], b[4];
      *(float4*)a = *(const float4*)(Qs + d*68 + 4*ty);
      *(float4*)b = *(const float4*)(Ks + d*68 + 4*tx);
      #pragma unroll
      for(int i=0;i<4;i++)
        #pragma unroll
        for(int j=0;j<4;j++) s[i][j] = fmaf(a[i], b[j], s[i][j]);
    }

    float ktv[4], ckv[4];
    #pragma unroll
    for(int j=0;j<4;j++){
      ktv[j] = kts[4*tx+j];
      ckv[j] = fmaxf(ktv[j], 1.0000001f);
    }

    float z[4][4];
    #pragma unroll
    for(int i=0;i<4;i++){
      #pragma unroll
      for(int j=0;j<4;j++){
        float rawc = fmaxf(qtv[i]*ktv[j] - s[i][j], 1.0f);
        bool selfp = rawc < 1.00001f;
        float c  = selfp ? 2.f : rawc;
        float sh = sqrtf((c-1.f)*(c+1.f));
        float dist = __logf(c + sh);
        float Z = (rawc*coshOQ[i] - ckv[j]) / (shOQ[i]*sh);
        Z = selfp ? 1.f : fminf(fmaxf(Z,-1.f),1.f);
        float dl = fminf(dist, 40.f);
        float pen = -lam*__logf(1.f + dl*dl);
        float ent = __logf(1.f + __expf(Bq[i] + Z - 0.1f)) - sp_m;
        z[i][j] = pen - tau*ent;
      }
    }

    #pragma unroll
    for(int i=0;i<4;i++){
      float mx = fmaxf(fmaxf(z[i][0],z[i][1]), fmaxf(z[i][2],z[i][3]));
      #pragma unroll
      for(int o=1;o<16;o<<=1) mx = fmaxf(mx, __shfl_xor_sync(0xffffffffu, mx, o));
      float mnew = fmaxf(mrow[i], mx);
      float sc = __expf(mrow[i] - mnew);
      float p[4], ps = 0.f;
      #pragma unroll
      for(int j=0;j<4;j++){ p[j] = __expf(z[i][j]-mnew); ps += p[j]; }
      #pragma unroll
      for(int o=1;o<16;o<<=1) ps += __shfl_xor_sync(0xffffffffu, ps, o);
      lrow[i] = lrow[i]*sc + ps;
      mrow[i] = mnew;
      #pragma unroll
      for(int c=0;c<4;c++) accO[i][c] *= sc;
      *(float4*)(Ps + (4*ty+i)*68 + 4*tx) = make_float4(p[0],p[1],p[2],p[3]);
    }
    __syncthreads();

    #pragma unroll 8
    for(int j=0;j<64;j++){
      float vv[4];
      *(float4*)vv = *(const float4*)(Vs + j*64 + 4*tx);
      #pragma unroll
      for(int i=0;i<4;i++){
        float pp = Ps[(4*ty+i)*68 + j];
        #pragma unroll
        for(int c=0;c<4;c++) accO[i][c] = fmaf(pp, vv[c], accO[i][c]);
      }
    }
  }

  int b_ = bh / HEADS, h = bh % HEADS;
  #pragma unroll
  for(int i=0;i<4;i++){
    float inv = 1.f/(lrow[i]*(1.f + 1e-8f));
    float ag[4]; float nn = 0.f;
    #pragma unroll
    for(int c=0;c<4;c++){ ag[c] = accO[i][c]*inv; nn += ag[c]*ag[c]; }
    #pragma unroll
    for(int o=1;o<16;o<<=1) nn += __shfl_xor_sync(0xffffffffu, nn, o);
    nn = sqrtf(nn);
    float tcosh = coshf(nn);
    float scl = sinhf(nn)/fmaxf(nn, 1e-8f);
    int grow = b_*SEQ + it*64 + 4*ty + i;
    #pragma unroll
    for(int c=0;c<4;c++){
      size_t idx = (size_t)grow*KP1 + 1 + h*HDIM + 4*tx + c;
      splitStore(g_AINh + idx, g_AINl + idx, ag[c]*scl);
    }
    if(tx==0) g_Th[grow*HEADS + h] = tcosh;
  }
}

// t_new = sqrt(sum_h t_h^2 - (H-1)*K) -> AIN time col (split)
__global__ void tnew_kernel()
{
  int r = blockIdx.x*256 + threadIdx.x;
  if(r >= ROWS) return;
  float s = 0.f;
  #pragma unroll
  for(int h=0; h<HEADS; h++){ float t = g_Th[r*HEADS+h]; s += t*t; }
  splitStore(g_AINh + (size_t)r*KP1, g_AINl + (size_t)r*KP1, sqrtf(s - (float)(HEADS-1)));
}

// time col for mlp hidden (reads split planes)
__global__ void time_mlp_kernel()
{
  __shared__ float red[8];
  int row = blockIdx.x, tid = threadIdx.x;
  float s = 0.f;
  #pragma unroll
  for(int q=0;q<12;q++){
    size_t idx = (size_t)row*KP2 + 1 + tid + q*256;
    float x = __bfloat162float(g_H1h[idx]) + __bfloat162float(g_H1l[idx]);
    s += x*x;
  }
  s = blockSum(s, red);
  if(tid==0) splitStore(g_H1h + (size_t)row*KP2, g_H1l + (size_t)row*KP2, sqrtf(1.f + s));
}

// final: res = G2 + OUT; d_out = [sqrt(1+|res|^2), res]
__global__ void final_kernel(float* __restrict__ out)
{
  __shared__ float red[8];
  int row = blockIdx.x, tid = threadIdx.x;
  float v[3]; float s = 0.f;
  #pragma unroll
  for(int q=0;q<3;q++){
    int j = tid + q*256;
    float x = g_G2[(size_t)row*D + j] + g_OUT[(size_t)row*D + j];
    v[q] = x; s += x*x;
  }
  s = blockSum(s, red);
  #pragma unroll
  for(int q=0;q<3;q++){
    int j = tid + q*256;
    out[(size_t)row*DH + 1 + j] = v[q];
  }
  if(tid==0) out[(size_t)row*DH] = sqrtf(1.f + s);
}

// ---------------------------------------------------------------------------
// Launch
// ---------------------------------------------------------------------------
extern "C" void kernel_launch(void* const* d_in, const int* in_sizes, int n_in,
                              void* d_out, int out_size)
{
  const float* x    = (const float*)d_in[0];
  const float* Wq   = (const float*)d_in[1];
  const float* Wk   = (const float*)d_in[2];
  const float* Wv   = (const float*)d_in[3];
  const float* Wo   = (const float*)d_in[4];
  const float* ln1g = (const float*)d_in[5];
  const float* ln1b = (const float*)d_in[6];
  const float* ln2g = (const float*)d_in[7];
  const float* ln2b = (const float*)d_in[8];
  const float* Wm1  = (const float*)d_in[9];
  const float* Wm2  = (const float*)d_in[10];
  const float* araw = (const float*)d_in[11];
  const float* traw = (const float*)d_in[12];
  const float* lraw = (const float*)d_in[13];
  float* out = (float*)d_out;

  float *pQh, *pKh, *pVh, *pMO, *pOUT, *pG2;
  cudaGetSymbolAddress((void**)&pQh,  g_Qh);
  cudaGetSymbolAddress((void**)&pKh,  g_Kh);
  cudaGetSymbolAddress((void**)&pVh,  g_Vh);
  cudaGetSymbolAddress((void**)&pMO,  g_MO);
  cudaGetSymbolAddress((void**)&pOUT, g_OUT);
  cudaGetSymbolAddress((void**)&pG2,  g_G2);

  __nv_bfloat16 *pX1h,*pX1l,*pAINh,*pAINl,*pHh,*pHl,*pH1h,*pH1l;
  __nv_bfloat16 *pWqh,*pWql,*pWkh,*pWkl,*pWvh,*pWvl,*pWoh,*pWol,*pW1h,*pW1l,*pW2h,*pW2l;
  cudaGetSymbolAddress((void**)&pX1h,  g_X1h);  cudaGetSymbolAddress((void**)&pX1l,  g_X1l);
  cudaGetSymbolAddress((void**)&pAINh, g_AINh); cudaGetSymbolAddress((void**)&pAINl, g_AINl);
  cudaGetSymbolAddress((void**)&pHh,   g_Hh);   cudaGetSymbolAddress((void**)&pHl,   g_Hl);
  cudaGetSymbolAddress((void**)&pH1h,  g_H1h);  cudaGetSymbolAddress((void**)&pH1l,  g_H1l);
  cudaGetSymbolAddress((void**)&pWqh,  g_Wqh);  cudaGetSymbolAddress((void**)&pWql,  g_Wql);
  cudaGetSymbolAddress((void**)&pWkh,  g_Wkh);  cudaGetSymbolAddress((void**)&pWkl,  g_Wkl);
  cudaGetSymbolAddress((void**)&pWvh,  g_Wvh);  cudaGetSymbolAddress((void**)&pWvl,  g_Wvl);
  cudaGetSymbolAddress((void**)&pWoh,  g_Woh);  cudaGetSymbolAddress((void**)&pWol,  g_Wol);
  cudaGetSymbolAddress((void**)&pW1h,  g_W1h);  cudaGetSymbolAddress((void**)&pW1l,  g_W1l);
  cudaGetSymbolAddress((void**)&pW2h,  g_W2h);  cudaGetSymbolAddress((void**)&pW2l,  g_W2l);

  cudaFuncSetAttribute(attn_kernel, cudaFuncAttributeMaxDynamicSharedMemorySize,
                       ATT_SMEM_FLOATS*sizeof(float));
  cudaFuncSetAttribute(hgemm_kernel, cudaFuncAttributeMaxDynamicSharedMemorySize,
                       HG_SMEM_BYTES);

  // 0. weight split-conversions
  {
    int t1 = D*DH;
    convsplit_kernel<<<(t1+255)/256,256>>>(Wq, pWqh, pWql, DH, KP1, t1);
    convsplit_kernel<<<(t1+255)/256,256>>>(Wk, pWkh, pWkl, DH, KP1, t1);
    convsplit_kernel<<<(t1+255)/256,256>>>(Wv, pWvh, pWvl, DH, KP1, t1);
    convsplit_kernel<<<(t1+255)/256,256>>>(Wo, pWoh, pWol, DH, KP1, t1);
    int t2 = DM*DH;
    convsplit_kernel<<<(t2+255)/256,256>>>(Wm1, pW1h, pW1l, DH, KP1, t2);
    int t3 = D*DMH;
    convsplit_kernel<<<(t3+255)/256,256>>>(Wm2, pW2h, pW2l, DMH, KP2, t3);
  }

  // 1. ln1 + add_time -> X1 planes
  ln_addtime_kernel<<<ROWS,256>>>(x, DH, 1, nullptr, 0, 0, ln1g, ln1b, pX1h, pX1l, nullptr);

  // 2. QKV projections (tensor cores) -> per-head fp32
  dim3 g768(D/128, ROWS/128);
  hgemm_kernel<<<g768,256,HG_SMEM_BYTES>>>(pX1h,pX1l, pWqh,pWql, pQh,nullptr,nullptr, KP1, 0, 1);
  hgemm_kernel<<<g768,256,HG_SMEM_BYTES>>>(pX1h,pX1l, pWkh,pWkl, pKh,nullptr,nullptr, KP1, 0, 1);
  hgemm_kernel<<<g768,256,HG_SMEM_BYTES>>>(pX1h,pX1l, pWvh,pWvl, pVh,nullptr,nullptr, KP1, 0, 1);

  // 3. q_t, k_t, v_tan
  prep_kernel<<<(BH*SEQ)/8, 256>>>();

  // 4. fused hyperbolic attention -> AIN planes + Th
  attn_kernel<<<dim3(SEQ/64, BH), 256, ATT_SMEM_FLOATS*sizeof(float)>>>(araw, traw, lraw);

  // 5. t_new -> AIN time col
  tnew_kernel<<<ROWS/256, 256>>>();

  // 6. Wo projection -> MO fp32
  hgemm_kernel<<<g768,256,HG_SMEM_BYTES>>>(pAINh,pAINl, pWoh,pWol, pMO,nullptr,nullptr, KP1, D, 0);

  // 7. residual + ln2 + add_time -> H planes (and stash residual in OUT)
  ln_addtime_kernel<<<ROWS,256>>>(pMO, D, 0, x, DH, 1, ln2g, ln2b, pHh, pHl, pOUT);

  // 8. MLP up-projection with exact gelu -> H1 planes (spatial slots)
  dim3 g3072(DM/128, ROWS/128);
  hgemm_kernel<<<g3072,256,HG_SMEM_BYTES>>>(pHh,pHl, pW1h,pW1l, nullptr, pH1h+1, pH1l+1, KP1, KP2, 2);

  // 9. time col of mlp hidden
  time_mlp_kernel<<<ROWS,256>>>();

  // 10. MLP down-projection -> G2 fp32
  hgemm_kernel<<<g768,256,HG_SMEM_BYTES>>>(pH1h,pH1l, pW2h,pW2l, pG2,nullptr,nullptr, KP2, D, 0);

  // 11. final residual + add_time -> output
  final_kernel<<<ROWS,256>>>(out);
}

// round 5
// speedup vs baseline: 2.4038x; 1.1613x over previous
#include <cuda_runtime.h>
#include <cuda_bf16.h>
#include <math.h>
#include <cstdint>

// ---------------------------------------------------------------------------
// Problem constants
// ---------------------------------------------------------------------------
#define BATCH 4
#define SEQ   1024
#define D     768
#define DH    769
#define HEADS 12
#define HDIM  64
#define BH    (BATCH*HEADS)      // 48
#define ROWS  (BATCH*SEQ)        // 4096
#define DM    3072
#define DMH   3073
#define KP1   800
#define KP2   3104

// ---------------------------------------------------------------------------
// Scratch
// ---------------------------------------------------------------------------
__device__ float g_Qh [BH*SEQ*HDIM];
__device__ float g_Kh [BH*SEQ*HDIM];
__device__ float g_Vh [BH*SEQ*HDIM];
__device__ float g_qt [BH*SEQ];
__device__ float g_kt [BH*SEQ];
__device__ float g_Th [ROWS*HEADS];
__device__ float g_MO [ROWS*D];
__device__ float g_OUT[ROWS*D];
__device__ float g_G2 [ROWS*D];

// split-bf16 per-head planes for attention
__device__ __nv_bfloat16 g_Qsph[BH*SEQ*HDIM], g_Qspl[BH*SEQ*HDIM];
__device__ __nv_bfloat16 g_Ksph[BH*SEQ*HDIM], g_Kspl[BH*SEQ*HDIM];
__device__ __nv_bfloat16 g_Vsph[BH*SEQ*HDIM], g_Vspl[BH*SEQ*HDIM];

// split-bf16 activation planes
__device__ __nv_bfloat16 g_X1h [ROWS*KP1], g_X1l [ROWS*KP1];
__device__ __nv_bfloat16 g_AINh[ROWS*KP1], g_AINl[ROWS*KP1];
__device__ __nv_bfloat16 g_Hh  [ROWS*KP1], g_Hl  [ROWS*KP1];
__device__ __nv_bfloat16 g_H1h [ROWS*KP2], g_H1l [ROWS*KP2];

// split-bf16 weight planes
__device__ __nv_bfloat16 g_Wqh[D*KP1],  g_Wql[D*KP1];
__device__ __nv_bfloat16 g_Wkh[D*KP1],  g_Wkl[D*KP1];
__device__ __nv_bfloat16 g_Wvh[D*KP1],  g_Wvl[D*KP1];
__device__ __nv_bfloat16 g_Woh[D*KP1],  g_Wol[D*KP1];
__device__ __nv_bfloat16 g_W1h[DM*KP1], g_W1l[DM*KP1];
__device__ __nv_bfloat16 g_W2h[D*KP2],  g_W2l[D*KP2];

// ---------------------------------------------------------------------------
// Helpers
// ---------------------------------------------------------------------------
__device__ __forceinline__ float warpSum(float v){
  #pragma unroll
  for(int o=16;o>0;o>>=1) v += __shfl_xor_sync(0xffffffffu, v, o);
  return v;
}
__device__ __forceinline__ float blockSum(float v, float* sh){
  int lane = threadIdx.x & 31, w = threadIdx.x >> 5;
  v = warpSum(v);
  if(lane==0) sh[w] = v;
  __syncthreads();
  float r = (threadIdx.x < 8) ? sh[threadIdx.x] : 0.f;
  if(w==0) r = warpSum(r);
  if(threadIdx.x==0) sh[0] = r;
  __syncthreads();
  r = sh[0];
  __syncthreads();
  return r;
}
__device__ __forceinline__ void splitStore(__nv_bfloat16* ph, __nv_bfloat16* pl, float x){
  __nv_bfloat16 h = __float2bfloat16(x);
  *ph = h;
  *pl = __float2bfloat16(x - __bfloat162float(h));
}
__device__ __forceinline__ void packsplit(float a, float b, unsigned &h, unsigned &l){
  __nv_bfloat16 ha = __float2bfloat16(a), hb = __float2bfloat16(b);
  float ra = a - __bfloat162float(ha), rb = b - __bfloat162float(hb);
  __nv_bfloat162 hp; hp.x = ha; hp.y = hb;
  __nv_bfloat162 lp; lp.x = __float2bfloat16(ra); lp.y = __float2bfloat16(rb);
  h = *(unsigned*)&hp;
  l = *(unsigned*)&lp;
}
__device__ __forceinline__ void cpasync16(void* s, const void* g){
  unsigned int sa = (unsigned int)__cvta_generic_to_shared(s);
  asm volatile("cp.async.cg.shared.global [%0], [%1], 16;\n" :: "r"(sa), "l"(g));
}
#define CP_COMMIT asm volatile("cp.async.commit_group;\n")
#define CP_WAIT(n) asm volatile("cp.async.wait_group %0;\n" :: "n"(n))

__device__ __forceinline__ void mma16816(float* d, const unsigned* a, const unsigned* b){
  asm volatile("mma.sync.aligned.m16n8k16.row.col.f32.bf16.bf16.f32 "
    "{%0,%1,%2,%3},{%4,%5,%6,%7},{%8,%9},{%0,%1,%2,%3};"
    : "+f"(d[0]),"+f"(d[1]),"+f"(d[2]),"+f"(d[3])
    : "r"(a[0]),"r"(a[1]),"r"(a[2]),"r"(a[3]),"r"(b[0]),"r"(b[1]));
}

// ---------------------------------------------------------------------------
// Weight split-convert
// ---------------------------------------------------------------------------
__global__ void convsplit_kernel(const float* __restrict__ W,
                                 __nv_bfloat16* __restrict__ Wh,
                                 __nv_bfloat16* __restrict__ Wl,
                                 int Kk, int KPp, int total)
{
  int i = blockIdx.x*256 + threadIdx.x;
  if(i >= total) return;
  int r = i / Kk, c = i - r*Kk;
  float x = W[i];
  __nv_bfloat16 h = __float2bfloat16(x);
  Wh[(size_t)r*KPp + c] = h;
  Wl[(size_t)r*KPp + c] = __float2bfloat16(x - __bfloat162float(h));
}

// ---------------------------------------------------------------------------
// LayerNorm (+optional add) + add_time -> split planes
// ---------------------------------------------------------------------------
__global__ void ln_addtime_kernel(const float* __restrict__ in1, int ld1, int off1,
                                  const float* __restrict__ in2, int ld2, int off2,
                                  const float* __restrict__ gv, const float* __restrict__ bv,
                                  __nv_bfloat16* __restrict__ outh,
                                  __nv_bfloat16* __restrict__ outl,
                                  float* __restrict__ rawOut)
{
  __shared__ float red[8];
  int row = blockIdx.x, tid = threadIdx.x;
  float v[3];
  #pragma unroll
  for(int q=0;q<3;q++){
    int j = tid + q*256;
    float x = in1[(size_t)row*ld1 + off1 + j];
    if(in2) x += in2[(size_t)row*ld2 + off2 + j];
    v[q] = x;
    if(rawOut) rawOut[(size_t)row*D + j] = x;
  }
  float s  = v[0]+v[1]+v[2];
  float s2 = v[0]*v[0]+v[1]*v[1]+v[2]*v[2];
  s  = blockSum(s,  red);
  float mu = s * (1.f/768.f);
  s2 = blockSum(s2, red);
  float var = s2*(1.f/768.f) - mu*mu;
  float rstd = rsqrtf(var + 1e-5f);
  float w[3]; float n2 = 0.f;
  #pragma unroll
  for(int q=0;q<3;q++){
    int j = tid + q*256;
    w[q] = (v[q]-mu)*rstd*gv[j] + bv[j];
    n2 += w[q]*w[q];
  }
  n2 = blockSum(n2, red);
  #pragma unroll
  for(int q=0;q<3;q++){
    int j = tid + q*256;
    splitStore(outh + (size_t)row*KP1 + 1 + j, outl + (size_t)row*KP1 + 1 + j, w[q]);
  }
  if(tid==0) splitStore(outh + (size_t)row*KP1, outl + (size_t)row*KP1, sqrtf(1.f + n2));
}

// ---------------------------------------------------------------------------
// Tensor-core split-bf16 GEMM (verified)
// ---------------------------------------------------------------------------
#define HG_STAGE_BF16 (4*128*40)
#define HG_SMEM_BYTES (2*HG_STAGE_BF16*2)

__global__ void __launch_bounds__(256,1) hgemm_kernel(
    const __nv_bfloat16* __restrict__ Ah, const __nv_bfloat16* __restrict__ Al,
    const __nv_bfloat16* __restrict__ Bh, const __nv_bfloat16* __restrict__ Bl,
    float* __restrict__ Cf, __nv_bfloat16* __restrict__ Ch, __nv_bfloat16* __restrict__ Cl,
    int KP, int ldc, int mode)
{
  extern __shared__ __nv_bfloat16 smb[];
  int tid = threadIdx.x;
  int lane = tid & 31, wid = tid >> 5;
  int wm = wid >> 2, wn = wid & 3;
  int g = lane >> 2, t = lane & 3;
  int row0 = blockIdx.y*128, col0 = blockIdx.x*128;

  float acc[4][4][4];
  #pragma unroll
  for(int mi=0;mi<4;mi++)
    #pragma unroll
    for(int ni=0;ni<4;ni++)
      #pragma unroll
      for(int e=0;e<4;e++) acc[mi][ni][e]=0.f;

  const int niter = KP >> 5;

  {
    __nv_bfloat16* s = smb;
    #pragma unroll
    for(int q=0;q<2;q++){
      int ch = tid + q*256;
      int row = ch>>2, cc = (ch&3)*8;
      cpasync16(s +             row*40 + cc, Ah + (size_t)(row0+row)*KP + cc);
      cpasync16(s +  5120 +     row*40 + cc, Al + (size_t)(row0+row)*KP + cc);
      cpasync16(s + 10240 +     row*40 + cc, Bh + (size_t)(col0+row)*KP + cc);
      cpasync16(s + 15360 +     row*40 + cc, Bl + (size_t)(col0+row)*KP + cc);
    }
    CP_COMMIT;
  }

  for(int it=0; it<niter; it++){
    if(it+1 < niter){
      int k0 = (it+1) << 5;
      __nv_bfloat16* s = smb + ((it+1)&1)*HG_STAGE_BF16;
      #pragma unroll
      for(int q=0;q<2;q++){
        int ch = tid + q*256;
        int row = ch>>2, cc = (ch&3)*8;
        cpasync16(s +             row*40 + cc, Ah + (size_t)(row0+row)*KP + k0 + cc);
        cpasync16(s +  5120 +     row*40 + cc, Al + (size_t)(row0+row)*KP + k0 + cc);
        cpasync16(s + 10240 +     row*40 + cc, Bh + (size_t)(col0+row)*KP + k0 + cc);
        cpasync16(s + 15360 +     row*40 + cc, Bl + (size_t)(col0+row)*KP + k0 + cc);
      }
      CP_COMMIT;
      CP_WAIT(1);
    } else {
      CP_WAIT(0);
    }
    __syncthreads();

    const unsigned* pAh = (const unsigned*)(smb + (it&1)*HG_STAGE_BF16);
    const unsigned* pAl = pAh + 2560;
    const unsigned* pBh = pAh + 5120;
    const unsigned* pBl = pAh + 7680;

    #pragma unroll
    for(int ks=0;ks<2;ks++){
      unsigned a_h[4][4], a_l[4][4], b_h[4][2], b_l[4][2];
      #pragma unroll
      for(int mi=0;mi<4;mi++){
        int base = (wm*64 + mi*16 + g)*20 + ks*8 + t;
        a_h[mi][0]=pAh[base];     a_h[mi][1]=pAh[base+160];
        a_h[mi][2]=pAh[base+4];   a_h[mi][3]=pAh[base+164];
        a_l[mi][0]=pAl[base];     a_l[mi][1]=pAl[base+160];
        a_l[mi][2]=pAl[base+4];   a_l[mi][3]=pAl[base+164];
      }
      #pragma unroll
      for(int ni=0;ni<4;ni++){
        int base = (wn*32 + ni*8 + g)*20 + ks*8 + t;
        b_h[ni][0]=pBh[base];  b_h[ni][1]=pBh[base+4];
        b_l[ni][0]=pBl[base];  b_l[ni][1]=pBl[base+4];
      }
      #pragma unroll
      for(int mi=0;mi<4;mi++)
        #pragma unroll
        for(int ni=0;ni<4;ni++) mma16816(acc[mi][ni], a_h[mi], b_h[ni]);
      #pragma unroll
      for(int mi=0;mi<4;mi++)
        #pragma unroll
        for(int ni=0;ni<4;ni++) mma16816(acc[mi][ni], a_h[mi], b_l[ni]);
      #pragma unroll
      for(int mi=0;mi<4;mi++)
        #pragma unroll
        for(int ni=0;ni<4;ni++) mma16816(acc[mi][ni], a_l[mi], b_h[ni]);
    }
    __syncthreads();
  }

  #pragma unroll
  for(int mi=0;mi<4;mi++){
    int rb = row0 + wm*64 + mi*16 + g;
    #pragma unroll
    for(int ni=0;ni<4;ni++){
      int cb = col0 + wn*32 + ni*8 + 2*t;
      float* a = acc[mi][ni];
      #pragma unroll
      for(int e=0;e<4;e++){
        int r = rb + (e>=2 ? 8 : 0);
        int c = cb + (e&1);
        float v = a[e];
        if(mode==2){
          v = 0.5f*v*(1.f + erff(v*0.70710678118654752f));
          splitStore(Ch + (size_t)r*ldc + c, Cl + (size_t)r*ldc + c, v);
        } else if(mode==1){
          int b_ = r >> 10, ii = r & 1023;
          int h = c >> 6, cc2 = c & 63;
          Cf[(size_t)(((b_*HEADS+h)<<10) + ii)*HDIM + cc2] = v;
        } else {
          Cf[(size_t)r*ldc + c] = v;
        }
      }
    }
  }
}

// ---------------------------------------------------------------------------
// Prep: qt, kt, v->v_tan, and split-bf16 planes of Q, K, V_tan
// ---------------------------------------------------------------------------
__global__ void prep_kernel()
{
  int w = blockIdx.x*8 + (threadIdx.x>>5);
  int lane = threadIdx.x & 31;

  const float* q = g_Qh + (size_t)w*HDIM;
  float qv[2]; float s = 0.f;
  #pragma unroll
  for(int e=0;e<2;e++){ qv[e] = q[lane+32*e]; s += qv[e]*qv[e]; }
  s = warpSum(s);
  if(lane==0) g_qt[w] = sqrtf(1.f + s);
  #pragma unroll
  for(int e=0;e<2;e++)
    splitStore(g_Qsph + (size_t)w*HDIM + lane+32*e, g_Qspl + (size_t)w*HDIM + lane+32*e, qv[e]);

  const float* k = g_Kh + (size_t)w*HDIM;
  float kv[2]; s = 0.f;
  #pragma unroll
  for(int e=0;e<2;e++){ kv[e] = k[lane+32*e]; s += kv[e]*kv[e]; }
  s = warpSum(s);
  if(lane==0) g_kt[w] = sqrtf(1.f + s);
  #pragma unroll
  for(int e=0;e<2;e++)
    splitStore(g_Ksph + (size_t)w*HDIM + lane+32*e, g_Kspl + (size_t)w*HDIM + lane+32*e, kv[e]);

  const float* v = g_Vh + (size_t)w*HDIM;
  float vv[2]; s = 0.f;
  #pragma unroll
  for(int e=0;e<2;e++){ vv[e] = v[lane+32*e]; s += vv[e]*vv[e]; }
  s = warpSum(s);
  float sn = sqrtf(s);
  float vt = sqrtf(1.f + s);
  float vc = fmaxf(vt, 1.0000001f);
  float dist = __logf(vc + sqrtf((vc-1.f)*(vc+1.f)));
  float scl = dist / fmaxf(sn, 1e-8f);
  #pragma unroll
  for(int e=0;e<2;e++)
    splitStore(g_Vsph + (size_t)w*HDIM + lane+32*e, g_Vspl + (size_t)w*HDIM + lane+32*e, vv[e]*scl);
}

// ---------------------------------------------------------------------------
// Tensor-core fused hyperbolic flash attention.
//   Block = 128 q-rows x 1 bh. 8 warps, each warp 16 rows x full 64 cols.
// ---------------------------------------------------------------------------
#define AT_STR   72
#define AT_USTR  36

// Per-entry logit, with the reference's per-entry is_self threshold test
// (matches R3's verified numerics).
__device__ __forceinline__ float attn_logit(float sv, float qt, float cq, float rsh,
                                            float Bq, float ktj, float lam, float tau,
                                            float spm){
  float rawc = fmaxf(qt*ktj - sv, 1.0f);
  bool selfp = rawc < 1.00001f;
  float c = selfp ? 2.f : rawc;
  float x = (c-1.f)*(c+1.f);
  float rs = rsqrtf(fmaxf(x, 1e-12f));
  float sh = x*rs;                       // sinh(arccosh(c))
  float dist = __logf(c + sh);           // arccosh(c)
  float ck = fmaxf(ktj, 1.0000001f);
  float Z = (rawc*cq - ck)*rs*rsh;
  Z = selfp ? 1.f : fminf(fmaxf(Z, -1.f), 1.f);
  float pen = -lam*__logf(1.f + dist*dist);
  float ent = __logf(1.f + __expf(Bq + Z - 0.1f)) - spm;
  return pen - tau*ent;
}

__global__ void __launch_bounds__(256,1) attn_kernel(
    const float* __restrict__ alpha_raw,
    const float* __restrict__ tau_raw,
    const float* __restrict__ lambda_raw)
{
  __shared__ __nv_bfloat16 smK[4*64*AT_STR];   // Kh | Kl | VTh | VTl (Q staging reuses)
  __shared__ float kts[64];

  const int bh = blockIdx.y;
  const int qrow0 = blockIdx.x*128;
  const int tid = threadIdx.x;
  const int lane = tid & 31, wid = tid >> 5;
  const int g = lane >> 2, t = lane & 3;

  __nv_bfloat16* Khs = smK;
  __nv_bfloat16* Kls = smK + 64*AT_STR;
  __nv_bfloat16* VThs= smK + 2*64*AT_STR;
  __nv_bfloat16* VTls= smK + 3*64*AT_STR;

  const float alpha = log1pf(expf(alpha_raw[0]));
  const float tau   = log1pf(expf(tau_raw[0]));
  const float lam   = log1pf(expf(lambda_raw[0]));
  const float spm   = log1pf(expf(-0.1f));

  // ---- stage Q planes into smem, extract fragments ----
  {
    const __nv_bfloat16* gQh = g_Qsph + ((size_t)bh*SEQ + qrow0)*HDIM;
    const __nv_bfloat16* gQl = g_Qspl + ((size_t)bh*SEQ + qrow0)*HDIM;
    #pragma unroll
    for(int itn=0; itn<4; itn++){
      int ch = tid + itn*256;
      int r = ch >> 3, c0 = (ch & 7)*8;
      *(uint4*)(smK + r*AT_STR + c0) = *(const uint4*)(gQh + r*HDIM + c0);
      *(uint4*)(smK + 128*AT_STR + r*AT_STR + c0) = *(const uint4*)(gQl + r*HDIM + c0);
    }
  }
  __syncthreads();

  unsigned qh[4][4], ql[4][4];
  {
    const unsigned* pQh = (const unsigned*)smK;
    const unsigned* pQl = pQh + 128*AT_USTR;
    int rbase = wid*16 + g;
    #pragma unroll
    for(int ks=0; ks<4; ks++){
      int base = rbase*AT_USTR + ks*8 + t;
      qh[ks][0]=pQh[base];               qh[ks][1]=pQh[base+8*AT_USTR];
      qh[ks][2]=pQh[base+4];             qh[ks][3]=pQh[base+8*AT_USTR+4];
      ql[ks][0]=pQl[base];               ql[ks][1]=pQl[base+8*AT_USTR];
      ql[ks][2]=pQl[base+4];             ql[ks][3]=pQl[base+8*AT_USTR+4];
    }
  }

  // per-row scalars (rows g and g+8 of this warp's 16-row tile)
  const int rowL = qrow0 + wid*16 + g;
  const int rowH = rowL + 8;
  float qtL = g_qt[bh*SEQ + rowL], qtH = g_qt[bh*SEQ + rowH];
  float cqL = fmaxf(qtL, 1.0000001f), cqH = fmaxf(qtH, 1.0000001f);
  float ctL = fminf(__logf(cqL + sqrtf((cqL-1.f)*(cqL+1.f))), 40.f);
  float ctH = fminf(__logf(cqH + sqrtf((cqH-1.f)*(cqH+1.f))), 40.f);
  float rshL = 1.f/sinhf(ctL), rshH = 1.f/sinhf(ctH);
  float BqL = alpha*ctL/(1.f + alpha*ctL);
  float BqH = alpha*ctH/(1.f + alpha*ctH);

  float accO[8][4];
  #pragma unroll
  for(int ni=0;ni<8;ni++)
    #pragma unroll
    for(int e=0;e<4;e++) accO[ni][e]=0.f;
  float lsumL = 0.f, lsumH = 0.f;

  const __nv_bfloat16* gKh = g_Ksph + (size_t)bh*SEQ*HDIM;
  const __nv_bfloat16* gKl = g_Kspl + (size_t)bh*SEQ*HDIM;
  const __nv_bfloat16* gVh = g_Vsph + (size_t)bh*SEQ*HDIM;
  const __nv_bfloat16* gVl = g_Vspl + (size_t)bh*SEQ*HDIM;
  const float* gkt = g_kt + bh*SEQ;

  for(int jt=0; jt<16; jt++){
    const int jbase = jt*64;
    __syncthreads();
    // load K tiles direct, V tiles transposed
    #pragma unroll
    for(int itn=0; itn<2; itn++){
      int ch = tid + itn*256;
      int j = ch >> 3, c0 = (ch & 7)*8;
      *(uint4*)(Khs + j*AT_STR + c0) = *(const uint4*)(gKh + (size_t)(jbase+j)*HDIM + c0);
      *(uint4*)(Kls + j*AT_STR + c0) = *(const uint4*)(gKl + (size_t)(jbase+j)*HDIM + c0);
      uint4 vh = *(const uint4*)(gVh + (size_t)(jbase+j)*HDIM + c0);
      uint4 vl = *(const uint4*)(gVl + (size_t)(jbase+j)*HDIM + c0);
      const __nv_bfloat16* vhp = (const __nv_bfloat16*)&vh;
      const __nv_bfloat16* vlp = (const __nv_bfloat16*)&vl;
      #pragma unroll
      for(int e=0;e<8;e++){
        VThs[(c0+e)*AT_STR + j] = vhp[e];
        VTls[(c0+e)*AT_STR + j] = vlp[e];
      }
    }
    if(tid < 64) kts[tid] = gkt[jbase + tid];
    __syncthreads();

    // ---- S = Q.K^T (3-term split) ----
    float accS[8][4];
    #pragma unroll
    for(int ni=0;ni<8;ni++)
      #pragma unroll
      for(int e=0;e<4;e++) accS[ni][e]=0.f;

    const unsigned* pKh = (const unsigned*)Khs;
    const unsigned* pKl = (const unsigned*)Kls;
    #pragma unroll
    for(int ks=0; ks<4; ks++){
      #pragma unroll
      for(int ni=0; ni<8; ni++){
        int base = (ni*8+g)*AT_USTR + ks*8 + t;
        unsigned bhf[2] = { pKh[base], pKh[base+4] };
        unsigned blf[2] = { pKl[base], pKl[base+4] };
        mma16816(accS[ni], qh[ks], bhf);
        mma16816(accS[ni], qh[ks], blf);
        mma16816(accS[ni], ql[ks], bhf);
      }
    }

    // ---- logits + exp (fixed max 0; z bounded above by ~0.4) ----
    #pragma unroll
    for(int ni=0; ni<8; ni++){
      float2 ktp = *(const float2*)&kts[ni*8 + 2*t];
      float z0 = attn_logit(accS[ni][0], qtL, cqL, rshL, BqL, ktp.x, lam, tau, spm);
      float z1 = attn_logit(accS[ni][1], qtL, cqL, rshL, BqL, ktp.y, lam, tau, spm);
      float z2 = attn_logit(accS[ni][2], qtH, cqH, rshH, BqH, ktp.x, lam, tau, spm);
      float z3 = attn_logit(accS[ni][3], qtH, cqH, rshH, BqH, ktp.y, lam, tau, spm);
      float p0 = __expf(z0), p1 = __expf(z1), p2 = __expf(z2), p3 = __expf(z3);
      lsumL += p0 + p1;
      lsumH += p2 + p3;
      accS[ni][0]=p0; accS[ni][1]=p1; accS[ni][2]=p2; accS[ni][3]=p3;
    }

    // ---- O += P.V (3-term split), P frags from accS registers ----
    const unsigned* pVh = (const unsigned*)VThs;
    const unsigned* pVl = (const unsigned*)VTls;
    #pragma unroll
    for(int kc=0; kc<4; kc++){
      unsigned aP_h[4], aP_l[4];
      packsplit(accS[2*kc  ][0], accS[2*kc  ][1], aP_h[0], aP_l[0]);
      packsplit(accS[2*kc  ][2], accS[2*kc  ][3], aP_h[1], aP_l[1]);
      packsplit(accS[2*kc+1][0], accS[2*kc+1][1], aP_h[2], aP_l[2]);
      packsplit(accS[2*kc+1][2], accS[2*kc+1][3], aP_h[3], aP_l[3]);
      #pragma unroll
      for(int ni=0; ni<8; ni++){
        int base = (ni*8+g)*AT_USTR + kc*8 + t;
        unsigned bhf[2] = { pVh[base], pVh[base+4] };
        unsigned blf[2] = { pVl[base], pVl[base+4] };
        mma16816(accO[ni], aP_h, bhf);
        mma16816(accO[ni], aP_h, blf);
        mma16816(accO[ni], aP_l, bhf);
      }
    }
  }

  // ---- epilogue: reduce l over quad, normalize, expmap0, write AIN ----
  float lL = lsumL, lH = lsumH;
  #pragma unroll
  for(int o=1;o<4;o<<=1){
    lL += __shfl_xor_sync(0xffffffffu, lL, o);
    lH += __shfl_xor_sync(0xffffffffu, lH, o);
  }
  float invL = 1.f/(lL*(1.f + 1e-8f));
  float invH = 1.f/(lH*(1.f + 1e-8f));

  float agL[8][2], agH[8][2];
  float nnL = 0.f, nnH = 0.f;
  #pragma unroll
  for(int ni=0;ni<8;ni++){
    agL[ni][0] = accO[ni][0]*invL; agL[ni][1] = accO[ni][1]*invL;
    agH[ni][0] = accO[ni][2]*invH; agH[ni][1] = accO[ni][3]*invH;
    nnL += agL[ni][0]*agL[ni][0] + agL[ni][1]*agL[ni][1];
    nnH += agH[ni][0]*agH[ni][0] + agH[ni][1]*agH[ni][1];
  }
  #pragma unroll
  for(int o=1;o<4;o<<=1){
    nnL += __shfl_xor_sync(0xffffffffu, nnL, o);
    nnH += __shfl_xor_sync(0xffffffffu, nnH, o);
  }
  nnL = sqrtf(nnL); nnH = sqrtf(nnH);
  float tL = coshf(nnL), tH = coshf(nnH);
  float sclL = sinhf(nnL)/fmaxf(nnL, 1e-8f);
  float sclH = sinhf(nnH)/fmaxf(nnH, 1e-8f);

  const int b_ = bh / HEADS, h = bh % HEADS;
  const int growL = b_*SEQ + rowL, growH = b_*SEQ + rowH;
  #pragma unroll
  for(int ni=0;ni<8;ni++){
    int c0 = ni*8 + 2*t;
    size_t iL = (size_t)growL*KP1 + 1 + h*HDIM + c0;
    size_t iH = (size_t)growH*KP1 + 1 + h*HDIM + c0;
    splitStore(g_AINh + iL,     g_AINl + iL,     agL[ni][0]*sclL);
    splitStore(g_AINh + iL + 1, g_AINl + iL + 1, agL[ni][1]*sclL);
    splitStore(g_AINh + iH,     g_AINl + iH,     agH[ni][0]*sclH);
    splitStore(g_AINh + iH + 1, g_AINl + iH + 1, agH[ni][1]*sclH);
  }
  if(t==0){
    g_Th[growL*HEADS + h] = tL;
    g_Th[growH*HEADS + h] = tH;
  }
}

// t_new
__global__ void tnew_kernel()
{
  int r = blockIdx.x*256 + threadIdx.x;
  if(r >= ROWS) return;
  float s = 0.f;
  #pragma unroll
  for(int h=0; h<HEADS; h++){ float t = g_Th[r*HEADS+h]; s += t*t; }
  splitStore(g_AINh + (size_t)r*KP1, g_AINl + (size_t)r*KP1, sqrtf(s - (float)(HEADS-1)));
}

// time col for mlp hidden
__global__ void time_mlp_kernel()
{
  __shared__ float red[8];
  int row = blockIdx.x, tid = threadIdx.x;
  float s = 0.f;
  #pragma unroll
  for(int q=0;q<12;q++){
    size_t idx = (size_t)row*KP2 + 1 + tid + q*256;
    float x = __bfloat162float(g_H1h[idx]) + __bfloat162float(g_H1l[idx]);
    s += x*x;
  }
  s = blockSum(s, red);
  if(tid==0) splitStore(g_H1h + (size_t)row*KP2, g_H1l + (size_t)row*KP2, sqrtf(1.f + s));
}

// final
__global__ void final_kernel(float* __restrict__ out)
{
  __shared__ float red[8];
  int row = blockIdx.x, tid = threadIdx.x;
  float v[3]; float s = 0.f;
  #pragma unroll
  for(int q=0;q<3;q++){
    int j = tid + q*256;
    float x = g_G2[(size_t)row*D + j] + g_OUT[(size_t)row*D + j];
    v[q] = x; s += x*x;
  }
  s = blockSum(s, red);
  #pragma unroll
  for(int q=0;q<3;q++){
    int j = tid + q*256;
    out[(size_t)row*DH + 1 + j] = v[q];
  }
  if(tid==0) out[(size_t)row*DH] = sqrtf(1.f + s);
}

// ---------------------------------------------------------------------------
// Launch
// ---------------------------------------------------------------------------
extern "C" void kernel_launch(void* const* d_in, const int* in_sizes, int n_in,
                              void* d_out, int out_size)
{
  const float* x    = (const float*)d_in[0];
  const float* Wq   = (const float*)d_in[1];
  const float* Wk   = (const float*)d_in[2];
  const float* Wv   = (const float*)d_in[3];
  const float* Wo   = (const float*)d_in[4];
  const float* ln1g = (const float*)d_in[5];
  const float* ln1b = (const float*)d_in[6];
  const float* ln2g = (const float*)d_in[7];
  const float* ln2b = (const float*)d_in[8];
  const float* Wm1  = (const float*)d_in[9];
  const float* Wm2  = (const float*)d_in[10];
  const float* araw = (const float*)d_in[11];
  const float* traw = (const float*)d_in[12];
  const float* lraw = (const float*)d_in[13];
  float* out = (float*)d_out;

  float *pQh, *pKh, *pVh, *pMO, *pOUT, *pG2;
  cudaGetSymbolAddress((void**)&pQh,  g_Qh);
  cudaGetSymbolAddress((void**)&pKh,  g_Kh);
  cudaGetSymbolAddress((void**)&pVh,  g_Vh);
  cudaGetSymbolAddress((void**)&pMO,  g_MO);
  cudaGetSymbolAddress((void**)&pOUT, g_OUT);
  cudaGetSymbolAddress((void**)&pG2,  g_G2);

  __nv_bfloat16 *pX1h,*pX1l,*pAINh,*pAINl,*pHh,*pHl,*pH1h,*pH1l;
  __nv_bfloat16 *pWqh,*pWql,*pWkh,*pWkl,*pWvh,*pWvl,*pWoh,*pWol,*pW1h,*pW1l,*pW2h,*pW2l;
  cudaGetSymbolAddress((void**)&pX1h,  g_X1h);  cudaGetSymbolAddress((void**)&pX1l,  g_X1l);
  cudaGetSymbolAddress((void**)&pAINh, g_AINh); cudaGetSymbolAddress((void**)&pAINl, g_AINl);
  cudaGetSymbolAddress((void**)&pHh,   g_Hh);   cudaGetSymbolAddress((void**)&pHl,   g_Hl);
  cudaGetSymbolAddress((void**)&pH1h,  g_H1h);  cudaGetSymbolAddress((void**)&pH1l,  g_H1l);
  cudaGetSymbolAddress((void**)&pWqh,  g_Wqh);  cudaGetSymbolAddress((void**)&pWql,  g_Wql);
  cudaGetSymbolAddress((void**)&pWkh,  g_Wkh);  cudaGetSymbolAddress((void**)&pWkl,  g_Wkl);
  cudaGetSymbolAddress((void**)&pWvh,  g_Wvh);  cudaGetSymbolAddress((void**)&pWvl,  g_Wvl);
  cudaGetSymbolAddress((void**)&pWoh,  g_Woh);  cudaGetSymbolAddress((void**)&pWol,  g_Wol);
  cudaGetSymbolAddress((void**)&pW1h,  g_W1h);  cudaGetSymbolAddress((void**)&pW1l,  g_W1l);
  cudaGetSymbolAddress((void**)&pW2h,  g_W2h);  cudaGetSymbolAddress((void**)&pW2l,  g_W2l);

  cudaFuncSetAttribute(hgemm_kernel, cudaFuncAttributeMaxDynamicSharedMemorySize,
                       HG_SMEM_BYTES);

  // 0. weight split-conversions
  {
    int t1 = D*DH;
    convsplit_kernel<<<(t1+255)/256,256>>>(Wq, pWqh, pWql, DH, KP1, t1);
    convsplit_kernel<<<(t1+255)/256,256>>>(Wk, pWkh, pWkl, DH, KP1, t1);
    convsplit_kernel<<<(t1+255)/256,256>>>(Wv, pWvh, pWvl, DH, KP1, t1);
    convsplit_kernel<<<(t1+255)/256,256>>>(Wo, pWoh, pWol, DH, KP1, t1);
    int t2 = DM*DH;
    convsplit_kernel<<<(t2+255)/256,256>>>(Wm1, pW1h, pW1l, DH, KP1, t2);
    int t3 = D*DMH;
    convsplit_kernel<<<(t3+255)/256,256>>>(Wm2, pW2h, pW2l, DMH, KP2, t3);
  }

  // 1. ln1 + add_time
  ln_addtime_kernel<<<ROWS,256>>>(x, DH, 1, nullptr, 0, 0, ln1g, ln1b, pX1h, pX1l, nullptr);

  // 2. QKV projections
  dim3 g768(D/128, ROWS/128);
  hgemm_kernel<<<g768,256,HG_SMEM_BYTES>>>(pX1h,pX1l, pWqh,pWql, pQh,nullptr,nullptr, KP1, 0, 1);
  hgemm_kernel<<<g768,256,HG_SMEM_BYTES>>>(pX1h,pX1l, pWkh,pWkl, pKh,nullptr,nullptr, KP1, 0, 1);
  hgemm_kernel<<<g768,256,HG_SMEM_BYTES>>>(pX1h,pX1l, pWvh,pWvl, pVh,nullptr,nullptr, KP1, 0, 1);

  // 3. qt, kt, v_tan + split planes
  prep_kernel<<<(BH*SEQ)/8, 256>>>();

  // 4. tensor-core fused attention
  attn_kernel<<<dim3(SEQ/128, BH), 256>>>(araw, traw, lraw);

  // 5. t_new
  tnew_kernel<<<ROWS/256, 256>>>();

  // 6. Wo projection
  hgemm_kernel<<<g768,256,HG_SMEM_BYTES>>>(pAINh,pAINl, pWoh,pWol, pMO,nullptr,nullptr, KP1, D, 0);

  // 7. residual + ln2
  ln_addtime_kernel<<<ROWS,256>>>(pMO, D, 0, x, DH, 1, ln2g, ln2b, pHh, pHl, pOUT);

  // 8. MLP up with gelu
  dim3 g3072(DM/128, ROWS/128);
  hgemm_kernel<<<g3072,256,HG_SMEM_BYTES>>>(pHh,pHl, pW1h,pW1l, nullptr, pH1h+1, pH1l+1, KP1, KP2, 2);

  // 9. mlp hidden time col
  time_mlp_kernel<<<ROWS,256>>>();

  // 10. MLP down
  hgemm_kernel<<<g768,256,HG_SMEM_BYTES>>>(pH1h,pH1l, pW2h,pW2l, pG2,nullptr,nullptr, KP2, D, 0);

  // 11. final
  final_kernel<<<ROWS,256>>>(out);
}

// round 6
// speedup vs baseline: 2.5930x; 1.0787x over previous
#include <cuda_runtime.h>
#include <cuda_bf16.h>
#include <math.h>
#include <cstdint>

// ---------------------------------------------------------------------------
// Problem constants
// ---------------------------------------------------------------------------
#define BATCH 4
#define SEQ   1024
#define D     768
#define DH    769
#define HEADS 12
#define HDIM  64
#define BH    (BATCH*HEADS)      // 48
#define ROWS  (BATCH*SEQ)        // 4096
#define DM    3072
#define DMH   3073
#define KP1   800
#define KP2   3104

// ---------------------------------------------------------------------------
// Scratch
// ---------------------------------------------------------------------------
__device__ float g_QKVf[3*BH*SEQ*HDIM];   // Q | K | V per-head fp32
__device__ float g_qt [BH*SEQ];
__device__ float g_kt [BH*SEQ];
__device__ float g_Th [ROWS*HEADS];
__device__ float g_MO [ROWS*D];
__device__ float g_OUT[ROWS*D];
__device__ float g_G2 [ROWS*D];

// split-bf16 per-head planes for attention
__device__ __nv_bfloat16 g_Qsph[BH*SEQ*HDIM], g_Qspl[BH*SEQ*HDIM];
__device__ __nv_bfloat16 g_Ksph[BH*SEQ*HDIM], g_Kspl[BH*SEQ*HDIM];
__device__ __nv_bfloat16 g_Vsph[BH*SEQ*HDIM], g_Vspl[BH*SEQ*HDIM];

// split-bf16 activation planes
__device__ __nv_bfloat16 g_X1h [ROWS*KP1], g_X1l [ROWS*KP1];
__device__ __nv_bfloat16 g_AINh[ROWS*KP1], g_AINl[ROWS*KP1];
__device__ __nv_bfloat16 g_Hh  [ROWS*KP1], g_Hl  [ROWS*KP1];
__device__ __nv_bfloat16 g_H1h [ROWS*KP2], g_H1l [ROWS*KP2];

// split-bf16 weight planes
__device__ __nv_bfloat16 g_Wqkvh[3*D*KP1], g_Wqkvl[3*D*KP1];
__device__ __nv_bfloat16 g_Woh[D*KP1],  g_Wol[D*KP1];
__device__ __nv_bfloat16 g_W1h[DM*KP1], g_W1l[DM*KP1];
__device__ __nv_bfloat16 g_W2h[D*KP2],  g_W2l[D*KP2];

// ---------------------------------------------------------------------------
// Helpers
// ---------------------------------------------------------------------------
__device__ __forceinline__ float warpSum(float v){
  #pragma unroll
  for(int o=16;o>0;o>>=1) v += __shfl_xor_sync(0xffffffffu, v, o);
  return v;
}
__device__ __forceinline__ float blockSum(float v, float* sh){
  int lane = threadIdx.x & 31, w = threadIdx.x >> 5;
  v = warpSum(v);
  if(lane==0) sh[w] = v;
  __syncthreads();
  float r = (threadIdx.x < 8) ? sh[threadIdx.x] : 0.f;
  if(w==0) r = warpSum(r);
  if(threadIdx.x==0) sh[0] = r;
  __syncthreads();
  r = sh[0];
  __syncthreads();
  return r;
}
__device__ __forceinline__ void splitStore(__nv_bfloat16* ph, __nv_bfloat16* pl, float x){
  __nv_bfloat16 h = __float2bfloat16(x);
  *ph = h;
  *pl = __float2bfloat16(x - __bfloat162float(h));
}
__device__ __forceinline__ void packsplit(float a, float b, unsigned &h, unsigned &l){
  __nv_bfloat16 ha = __float2bfloat16(a), hb = __float2bfloat16(b);
  float ra = a - __bfloat162float(ha), rb = b - __bfloat162float(hb);
  __nv_bfloat162 hp; hp.x = ha; hp.y = hb;
  __nv_bfloat162 lp; lp.x = __float2bfloat16(ra); lp.y = __float2bfloat16(rb);
  h = *(unsigned*)&hp;
  l = *(unsigned*)&lp;
}
__device__ __forceinline__ void cpasync16(void* s, const void* g){
  unsigned int sa = (unsigned int)__cvta_generic_to_shared(s);
  asm volatile("cp.async.cg.shared.global [%0], [%1], 16;\n" :: "r"(sa), "l"(g));
}
#define CP_COMMIT asm volatile("cp.async.commit_group;\n")
#define CP_WAIT(n) asm volatile("cp.async.wait_group %0;\n" :: "n"(n))

__device__ __forceinline__ void mma16816(float* d, const unsigned* a, const unsigned* b){
  asm volatile("mma.sync.aligned.m16n8k16.row.col.f32.bf16.bf16.f32 "
    "{%0,%1,%2,%3},{%4,%5,%6,%7},{%8,%9},{%0,%1,%2,%3};"
    : "+f"(d[0]),"+f"(d[1]),"+f"(d[2]),"+f"(d[3])
    : "r"(a[0]),"r"(a[1]),"r"(a[2]),"r"(a[3]),"r"(b[0]),"r"(b[1]));
}
__device__ __forceinline__ void ldsm4(unsigned* r, unsigned addr){
  asm volatile("ldmatrix.sync.aligned.m8n8.x4.shared.b16 {%0,%1,%2,%3}, [%4];"
    : "=r"(r[0]),"=r"(r[1]),"=r"(r[2]),"=r"(r[3]) : "r"(addr));
}
__device__ __forceinline__ void ldsm2(unsigned* r, unsigned addr){
  asm volatile("ldmatrix.sync.aligned.m8n8.x2.shared.b16 {%0,%1}, [%2];"
    : "=r"(r[0]),"=r"(r[1]) : "r"(addr));
}

// ---------------------------------------------------------------------------
// Weight split-converts
// ---------------------------------------------------------------------------
__global__ void convsplit_kernel(const float* __restrict__ W,
                                 __nv_bfloat16* __restrict__ Wh,
                                 __nv_bfloat16* __restrict__ Wl,
                                 int Kk, int KPp, int total)
{
  int i = blockIdx.x*256 + threadIdx.x;
  if(i >= total) return;
  int r = i / Kk, c = i - r*Kk;
  float x = W[i];
  __nv_bfloat16 h = __float2bfloat16(x);
  Wh[(size_t)r*KPp + c] = h;
  Wl[(size_t)r*KPp + c] = __float2bfloat16(x - __bfloat162float(h));
}

__global__ void convsplit_qkv_kernel(const float* __restrict__ Wq,
                                     const float* __restrict__ Wk,
                                     const float* __restrict__ Wv,
                                     __nv_bfloat16* __restrict__ Wh,
                                     __nv_bfloat16* __restrict__ Wl)
{
  int i = blockIdx.x*256 + threadIdx.x;
  if(i >= 3*D*DH) return;
  int r = i / DH, c = i - r*DH;
  const float* src = (r < D) ? Wq : ((r < 2*D) ? Wk : Wv);
  int rl = (r < D) ? r : ((r < 2*D) ? r - D : r - 2*D);
  float x = src[(size_t)rl*DH + c];
  __nv_bfloat16 h = __float2bfloat16(x);
  Wh[(size_t)r*KP1 + c] = h;
  Wl[(size_t)r*KP1 + c] = __float2bfloat16(x - __bfloat162float(h));
}

// ---------------------------------------------------------------------------
// LayerNorm (+optional add) + add_time -> split planes
// ---------------------------------------------------------------------------
__global__ void ln_addtime_kernel(const float* __restrict__ in1, int ld1, int off1,
                                  const float* __restrict__ in2, int ld2, int off2,
                                  const float* __restrict__ gv, const float* __restrict__ bv,
                                  __nv_bfloat16* __restrict__ outh,
                                  __nv_bfloat16* __restrict__ outl,
                                  float* __restrict__ rawOut)
{
  __shared__ float red[8];
  int row = blockIdx.x, tid = threadIdx.x;
  float v[3];
  #pragma unroll
  for(int q=0;q<3;q++){
    int j = tid + q*256;
    float x = in1[(size_t)row*ld1 + off1 + j];
    if(in2) x += in2[(size_t)row*ld2 + off2 + j];
    v[q] = x;
    if(rawOut) rawOut[(size_t)row*D + j] = x;
  }
  float s  = v[0]+v[1]+v[2];
  float s2 = v[0]*v[0]+v[1]*v[1]+v[2]*v[2];
  s  = blockSum(s,  red);
  float mu = s * (1.f/768.f);
  s2 = blockSum(s2, red);
  float var = s2*(1.f/768.f) - mu*mu;
  float rstd = rsqrtf(var + 1e-5f);
  float w[3]; float n2 = 0.f;
  #pragma unroll
  for(int q=0;q<3;q++){
    int j = tid + q*256;
    w[q] = (v[q]-mu)*rstd*gv[j] + bv[j];
    n2 += w[q]*w[q];
  }
  n2 = blockSum(n2, red);
  #pragma unroll
  for(int q=0;q<3;q++){
    int j = tid + q*256;
    splitStore(outh + (size_t)row*KP1 + 1 + j, outl + (size_t)row*KP1 + 1 + j, w[q]);
  }
  if(tid==0) splitStore(outh + (size_t)row*KP1, outl + (size_t)row*KP1, sqrtf(1.f + n2));
}

// ---------------------------------------------------------------------------
// Tensor-core split-bf16 GEMM: C[M,N] = A[M,K]*B[N,K]^T
//   128x128 CTA tile, BK=32, 8 warps, 64x32 warp tile,
//   3-stage cp.async pipeline, ldmatrix fragment loads.
//   mode 0: fp32 out (ldc); 1: fused-QKV head-scatter; 2: gelu + split out.
// ---------------------------------------------------------------------------
#define HG_STAGE_BF16 20480
#define HG_STAGE_BYTES 40960
#define HG_SMEM_BYTES (3*HG_STAGE_BYTES)

__global__ void __launch_bounds__(256,1) hgemm_kernel(
    const __nv_bfloat16* __restrict__ Ah, const __nv_bfloat16* __restrict__ Al,
    const __nv_bfloat16* __restrict__ Bh, const __nv_bfloat16* __restrict__ Bl,
    float* __restrict__ Cf, __nv_bfloat16* __restrict__ Ch, __nv_bfloat16* __restrict__ Cl,
    int KP, int ldc, int mode)
{
  extern __shared__ __nv_bfloat16 smb[];
  int tid = threadIdx.x;
  int lane = tid & 31, wid = tid >> 5;
  int wm = wid >> 2, wn = wid & 3;
  int g = lane >> 2, t = lane & 3;
  int row0 = blockIdx.y*128, col0 = blockIdx.x*128;

  float acc[4][4][4];
  #pragma unroll
  for(int mi=0;mi<4;mi++)
    #pragma unroll
    for(int ni=0;ni<4;ni++)
      #pragma unroll
      for(int e=0;e<4;e++) acc[mi][ni][e]=0.f;

  const int niter = KP >> 5;
  const unsigned smemU = (unsigned)__cvta_generic_to_shared(smb);

  // ldmatrix per-lane address offsets (bytes, relative to stage base)
  const int aRow = wm*64 + (lane&7) + ((lane>>3)&1)*8;
  const int aCol = ((lane>>4)&1)*8;
  const unsigned aOffH = (unsigned)((aRow*40 + aCol)*2);
  const int bRow = wn*32 + (lane&7);
  const int bCol = ((lane>>3)&1)*8;
  const unsigned bOffH = (unsigned)((bRow*40 + bCol)*2 + 20480);

  // stage loader
  int ldrow = tid >> 2, ldcc = (tid & 3)*8;
  int ldrow2 = (tid+256) >> 2, ldcc2 = ((tid+256) & 3)*8;

  #define LOAD_STAGE(stg, k0) do{                                             \
    __nv_bfloat16* s = smb + (stg)*HG_STAGE_BF16;                             \
    cpasync16(s +          ldrow*40 + ldcc,  Ah + (size_t)(row0+ldrow)*KP + (k0) + ldcc);  \
    cpasync16(s +  5120 +  ldrow*40 + ldcc,  Al + (size_t)(row0+ldrow)*KP + (k0) + ldcc);  \
    cpasync16(s + 10240 +  ldrow*40 + ldcc,  Bh + (size_t)(col0+ldrow)*KP + (k0) + ldcc);  \
    cpasync16(s + 15360 +  ldrow*40 + ldcc,  Bl + (size_t)(col0+ldrow)*KP + (k0) + ldcc);  \
    cpasync16(s +          ldrow2*40 + ldcc2, Ah + (size_t)(row0+ldrow2)*KP + (k0) + ldcc2);\
    cpasync16(s +  5120 +  ldrow2*40 + ldcc2, Al + (size_t)(row0+ldrow2)*KP + (k0) + ldcc2);\
    cpasync16(s + 10240 +  ldrow2*40 + ldcc2, Bh + (size_t)(col0+ldrow2)*KP + (k0) + ldcc2);\
    cpasync16(s + 15360 +  ldrow2*40 + ldcc2, Bl + (size_t)(col0+ldrow2)*KP + (k0) + ldcc2);\
    CP_COMMIT;                                                                \
  } while(0)

  LOAD_STAGE(0, 0);
  LOAD_STAGE(1, 32);

  for(int it=0; it<niter; it++){
    if(it+2 < niter){
      LOAD_STAGE((it+2)%3, (it+2)<<5);
      CP_WAIT(2);
    } else {
      CP_WAIT(0);
    }
    __syncthreads();

    const unsigned sb = smemU + (unsigned)((it%3)*HG_STAGE_BYTES);

    #pragma unroll
    for(int ks=0;ks<2;ks++){
      unsigned a_h[4][4], a_l[4][4];
      #pragma unroll
      for(int mi=0;mi<4;mi++){
        unsigned ad = sb + aOffH + (unsigned)(mi*1280 + ks*32);
        ldsm4(a_h[mi], ad);
        ldsm4(a_l[mi], ad + 10240);
      }
      unsigned b_h[4][2], b_l[4][2];
      #pragma unroll
      for(int ni=0;ni<4;ni++){
        unsigned bd = sb + bOffH + (unsigned)(ni*640 + ks*32);
        ldsm2(b_h[ni], bd);
        ldsm2(b_l[ni], bd + 10240);
      }
      #pragma unroll
      for(int mi=0;mi<4;mi++)
        #pragma unroll
        for(int ni=0;ni<4;ni++) mma16816(acc[mi][ni], a_h[mi], b_h[ni]);
      #pragma unroll
      for(int mi=0;mi<4;mi++)
        #pragma unroll
        for(int ni=0;ni<4;ni++) mma16816(acc[mi][ni], a_h[mi], b_l[ni]);
      #pragma unroll
      for(int mi=0;mi<4;mi++)
        #pragma unroll
        for(int ni=0;ni<4;ni++) mma16816(acc[mi][ni], a_l[mi], b_h[ni]);
    }
    __syncthreads();
  }

  // ---- epilogue ----
  int mat = blockIdx.x / 6;            // only used by mode 1 (N=2304 fused QKV)
  int cmatBase = mat*768;
  #pragma unroll
  for(int mi=0;mi<4;mi++){
    int rb = row0 + wm*64 + mi*16 + g;
    #pragma unroll
    for(int ni=0;ni<4;ni++){
      int cb = col0 + wn*32 + ni*8 + 2*t;
      float* a = acc[mi][ni];
      #pragma unroll
      for(int e=0;e<4;e++){
        int r = rb + (e>=2 ? 8 : 0);
        int c = cb + (e&1);
        float v = a[e];
        if(mode==2){
          v = 0.5f*v*(1.f + erff(v*0.70710678118654752f));
          splitStore(Ch + (size_t)r*ldc + c, Cl + (size_t)r*ldc + c, v);
        } else if(mode==1){
          int b_ = r >> 10, ii = r & 1023;
          int cmat = c - cmatBase;
          int h = cmat >> 6, cc2 = cmat & 63;
          Cf[(size_t)mat*(BH*SEQ*HDIM) + (size_t)(((b_*HEADS+h)<<10) + ii)*HDIM + cc2] = v;
        } else {
          Cf[(size_t)r*ldc + c] = v;
        }
      }
    }
  }
}

// ---------------------------------------------------------------------------
// Prep: qt, kt, v->v_tan, and split-bf16 planes of Q, K, V_tan
// ---------------------------------------------------------------------------
__global__ void prep_kernel()
{
  int w = blockIdx.x*8 + (threadIdx.x>>5);
  int lane = threadIdx.x & 31;

  const float* q = g_QKVf + (size_t)w*HDIM;
  float qv[2]; float s = 0.f;
  #pragma unroll
  for(int e=0;e<2;e++){ qv[e] = q[lane+32*e]; s += qv[e]*qv[e]; }
  s = warpSum(s);
  if(lane==0) g_qt[w] = sqrtf(1.f + s);
  #pragma unroll
  for(int e=0;e<2;e++)
    splitStore(g_Qsph + (size_t)w*HDIM + lane+32*e, g_Qspl + (size_t)w*HDIM + lane+32*e, qv[e]);

  const float* k = g_QKVf + (size_t)(BH*SEQ)*HDIM + (size_t)w*HDIM;
  float kv[2]; s = 0.f;
  #pragma unroll
  for(int e=0;e<2;e++){ kv[e] = k[lane+32*e]; s += kv[e]*kv[e]; }
  s = warpSum(s);
  if(lane==0) g_kt[w] = sqrtf(1.f + s);
  #pragma unroll
  for(int e=0;e<2;e++)
    splitStore(g_Ksph + (size_t)w*HDIM + lane+32*e, g_Kspl + (size_t)w*HDIM + lane+32*e, kv[e]);

  const float* v = g_QKVf + (size_t)(2*BH*SEQ)*HDIM + (size_t)w*HDIM;
  float vv[2]; s = 0.f;
  #pragma unroll
  for(int e=0;e<2;e++){ vv[e] = v[lane+32*e]; s += vv[e]*vv[e]; }
  s = warpSum(s);
  float sn = sqrtf(s);
  float vt = sqrtf(1.f + s);
  float vc = fmaxf(vt, 1.0000001f);
  float dist = __logf(vc + sqrtf((vc-1.f)*(vc+1.f)));
  float scl = dist / fmaxf(sn, 1e-8f);
  #pragma unroll
  for(int e=0;e<2;e++)
    splitStore(g_Vsph + (size_t)w*HDIM + lane+32*e, g_Vspl + (size_t)w*HDIM + lane+32*e, vv[e]*scl);
}

// ---------------------------------------------------------------------------
// Tensor-core fused hyperbolic flash attention (verified R5 numerics).
// ---------------------------------------------------------------------------
#define AT_STR   72
#define AT_USTR  36

__device__ __forceinline__ float attn_logit(float sv, float qt, float cq, float rsh,
                                            float Bq, float ktj, float lam, float tau,
                                            float spm){
  float rawc = fmaxf(qt*ktj - sv, 1.0f);
  bool selfp = rawc < 1.00001f;
  float c = selfp ? 2.f : rawc;
  float x = (c-1.f)*(c+1.f);
  float rs = rsqrtf(fmaxf(x, 1e-12f));
  float sh = x*rs;
  float dist = __logf(c + sh);
  float ck = fmaxf(ktj, 1.0000001f);
  float Z = (rawc*cq - ck)*rs*rsh;
  Z = selfp ? 1.f : fminf(fmaxf(Z, -1.f), 1.f);
  float pen = -lam*__logf(1.f + dist*dist);
  float ent = __logf(1.f + __expf(Bq + Z - 0.1f)) - spm;
  return pen - tau*ent;
}

__global__ void __launch_bounds__(256,1) attn_kernel(
    const float* __restrict__ alpha_raw,
    const float* __restrict__ tau_raw,
    const float* __restrict__ lambda_raw)
{
  __shared__ __nv_bfloat16 smK[4*64*AT_STR];
  __shared__ float kts[64];

  const int bh = blockIdx.y;
  const int qrow0 = blockIdx.x*128;
  const int tid = threadIdx.x;
  const int lane = tid & 31, wid = tid >> 5;
  const int g = lane >> 2, t = lane & 3;

  __nv_bfloat16* Khs = smK;
  __nv_bfloat16* Kls = smK + 64*AT_STR;
  __nv_bfloat16* VThs= smK + 2*64*AT_STR;
  __nv_bfloat16* VTls= smK + 3*64*AT_STR;

  const float alpha = log1pf(expf(alpha_raw[0]));
  const float tau   = log1pf(expf(tau_raw[0]));
  const float lam   = log1pf(expf(lambda_raw[0]));
  const float spm   = log1pf(expf(-0.1f));

  {
    const __nv_bfloat16* gQh = g_Qsph + ((size_t)bh*SEQ + qrow0)*HDIM;
    const __nv_bfloat16* gQl = g_Qspl + ((size_t)bh*SEQ + qrow0)*HDIM;
    #pragma unroll
    for(int itn=0; itn<4; itn++){
      int ch = tid + itn*256;
      int r = ch >> 3, c0 = (ch & 7)*8;
      *(uint4*)(smK + r*AT_STR + c0) = *(const uint4*)(gQh + r*HDIM + c0);
      *(uint4*)(smK + 128*AT_STR + r*AT_STR + c0) = *(const uint4*)(gQl + r*HDIM + c0);
    }
  }
  __syncthreads();

  unsigned qh[4][4], ql[4][4];
  {
    const unsigned* pQh = (const unsigned*)smK;
    const unsigned* pQl = pQh + 128*AT_USTR;
    int rbase = wid*16 + g;
    #pragma unroll
    for(int ks=0; ks<4; ks++){
      int base = rbase*AT_USTR + ks*8 + t;
      qh[ks][0]=pQh[base];               qh[ks][1]=pQh[base+8*AT_USTR];
      qh[ks][2]=pQh[base+4];             qh[ks][3]=pQh[base+8*AT_USTR+4];
      ql[ks][0]=pQl[base];               ql[ks][1]=pQl[base+8*AT_USTR];
      ql[ks][2]=pQl[base+4];             ql[ks][3]=pQl[base+8*AT_USTR+4];
    }
  }

  const int rowL = qrow0 + wid*16 + g;
  const int rowH = rowL + 8;
  float qtL = g_qt[bh*SEQ + rowL], qtH = g_qt[bh*SEQ + rowH];
  float cqL = fmaxf(qtL, 1.0000001f), cqH = fmaxf(qtH, 1.0000001f);
  float ctL = fminf(__logf(cqL + sqrtf((cqL-1.f)*(cqL+1.f))), 40.f);
  float ctH = fminf(__logf(cqH + sqrtf((cqH-1.f)*(cqH+1.f))), 40.f);
  float rshL = 1.f/sinhf(ctL), rshH = 1.f/sinhf(ctH);
  float BqL = alpha*ctL/(1.f + alpha*ctL);
  float BqH = alpha*ctH/(1.f + alpha*ctH);

  float accO[8][4];
  #pragma unroll
  for(int ni=0;ni<8;ni++)
    #pragma unroll
    for(int e=0;e<4;e++) accO[ni][e]=0.f;
  float lsumL = 0.f, lsumH = 0.f;

  const __nv_bfloat16* gKh = g_Ksph + (size_t)bh*SEQ*HDIM;
  const __nv_bfloat16* gKl = g_Kspl + (size_t)bh*SEQ*HDIM;
  const __nv_bfloat16* gVh = g_Vsph + (size_t)bh*SEQ*HDIM;
  const __nv_bfloat16* gVl = g_Vspl + (size_t)bh*SEQ*HDIM;
  const float* gkt = g_kt + bh*SEQ;

  for(int jt=0; jt<16; jt++){
    const int jbase = jt*64;
    __syncthreads();
    #pragma unroll
    for(int itn=0; itn<2; itn++){
      int ch = tid + itn*256;
      int j = ch >> 3, c0 = (ch & 7)*8;
      *(uint4*)(Khs + j*AT_STR + c0) = *(const uint4*)(gKh + (size_t)(jbase+j)*HDIM + c0);
      *(uint4*)(Kls + j*AT_STR + c0) = *(const uint4*)(gKl + (size_t)(jbase+j)*HDIM + c0);
      uint4 vh = *(const uint4*)(gVh + (size_t)(jbase+j)*HDIM + c0);
      uint4 vl = *(const uint4*)(gVl + (size_t)(jbase+j)*HDIM + c0);
      const __nv_bfloat16* vhp = (const __nv_bfloat16*)&vh;
      const __nv_bfloat16* vlp = (const __nv_bfloat16*)&vl;
      #pragma unroll
      for(int e=0;e<8;e++){
        VThs[(c0+e)*AT_STR + j] = vhp[e];
        VTls[(c0+e)*AT_STR + j] = vlp[e];
      }
    }
    if(tid < 64) kts[tid] = gkt[jbase + tid];
    __syncthreads();

    float accS[8][4];
    #pragma unroll
    for(int ni=0;ni<8;ni++)
      #pragma unroll
      for(int e=0;e<4;e++) accS[ni][e]=0.f;

    const unsigned* pKh = (const unsigned*)Khs;
    const unsigned* pKl = (const unsigned*)Kls;
    #pragma unroll
    for(int ks=0; ks<4; ks++){
      #pragma unroll
      for(int ni=0; ni<8; ni++){
        int base = (ni*8+g)*AT_USTR + ks*8 + t;
        unsigned bhf[2] = { pKh[base], pKh[base+4] };
        unsigned blf[2] = { pKl[base], pKl[base+4] };
        mma16816(accS[ni], qh[ks], bhf);
        mma16816(accS[ni], qh[ks], blf);
        mma16816(accS[ni], ql[ks], bhf);
      }
    }

    #pragma unroll
    for(int ni=0; ni<8; ni++){
      float2 ktp = *(const float2*)&kts[ni*8 + 2*t];
      float z0 = attn_logit(accS[ni][0], qtL, cqL, rshL, BqL, ktp.x, lam, tau, spm);
      float z1 = attn_logit(accS[ni][1], qtL, cqL, rshL, BqL, ktp.y, lam, tau, spm);
      float z2 = attn_logit(accS[ni][2], qtH, cqH, rshH, BqH, ktp.x, lam, tau, spm);
      float z3 = attn_logit(accS[ni][3], qtH, cqH, rshH, BqH, ktp.y, lam, tau, spm);
      float p0 = __expf(z0), p1 = __expf(z1), p2 = __expf(z2), p3 = __expf(z3);
      lsumL += p0 + p1;
      lsumH += p2 + p3;
      accS[ni][0]=p0; accS[ni][1]=p1; accS[ni][2]=p2; accS[ni][3]=p3;
    }

    const unsigned* pVh = (const unsigned*)VThs;
    const unsigned* pVl = (const unsigned*)VTls;
    #pragma unroll
    for(int kc=0; kc<4; kc++){
      unsigned aP_h[4], aP_l[4];
      packsplit(accS[2*kc  ][0], accS[2*kc  ][1], aP_h[0], aP_l[0]);
      packsplit(accS[2*kc  ][2], accS[2*kc  ][3], aP_h[1], aP_l[1]);
      packsplit(accS[2*kc+1][0], accS[2*kc+1][1], aP_h[2], aP_l[2]);
      packsplit(accS[2*kc+1][2], accS[2*kc+1][3], aP_h[3], aP_l[3]);
      #pragma unroll
      for(int ni=0; ni<8; ni++){
        int base = (ni*8+g)*AT_USTR + kc*8 + t;
        unsigned bhf[2] = { pVh[base], pVh[base+4] };
        unsigned blf[2] = { pVl[base], pVl[base+4] };
        mma16816(accO[ni], aP_h, bhf);
        mma16816(accO[ni], aP_h, blf);
        mma16816(accO[ni], aP_l, bhf);
      }
    }
  }

  float lL = lsumL, lH = lsumH;
  #pragma unroll
  for(int o=1;o<4;o<<=1){
    lL += __shfl_xor_sync(0xffffffffu, lL, o);
    lH += __shfl_xor_sync(0xffffffffu, lH, o);
  }
  float invL = 1.f/(lL*(1.f + 1e-8f));
  float invH = 1.f/(lH*(1.f + 1e-8f));

  float agL[8][2], agH[8][2];
  float nnL = 0.f, nnH = 0.f;
  #pragma unroll
  for(int ni=0;ni<8;ni++){
    agL[ni][0] = accO[ni][0]*invL; agL[ni][1] = accO[ni][1]*invL;
    agH[ni][0] = accO[ni][2]*invH; agH[ni][1] = accO[ni][3]*invH;
    nnL += agL[ni][0]*agL[ni][0] + agL[ni][1]*agL[ni][1];
    nnH += agH[ni][0]*agH[ni][0] + agH[ni][1]*agH[ni][1];
  }
  #pragma unroll
  for(int o=1;o<4;o<<=1){
    nnL += __shfl_xor_sync(0xffffffffu, nnL, o);
    nnH += __shfl_xor_sync(0xffffffffu, nnH, o);
  }
  nnL = sqrtf(nnL); nnH = sqrtf(nnH);
  float tL = coshf(nnL), tH = coshf(nnH);
  float sclL = sinhf(nnL)/fmaxf(nnL, 1e-8f);
  float sclH = sinhf(nnH)/fmaxf(nnH, 1e-8f);

  const int b_ = bh / HEADS, h = bh % HEADS;
  const int growL = b_*SEQ + rowL, growH = b_*SEQ + rowH;
  #pragma unroll
  for(int ni=0;ni<8;ni++){
    int c0 = ni*8 + 2*t;
    size_t iL = (size_t)growL*KP1 + 1 + h*HDIM + c0;
    size_t iH = (size_t)growH*KP1 + 1 + h*HDIM + c0;
    splitStore(g_AINh + iL,     g_AINl + iL,     agL[ni][0]*sclL);
    splitStore(g_AINh + iL + 1, g_AINl + iL + 1, agL[ni][1]*sclL);
    splitStore(g_AINh + iH,     g_AINl + iH,     agH[ni][0]*sclH);
    splitStore(g_AINh + iH + 1, g_AINl + iH + 1, agH[ni][1]*sclH);
  }
  if(t==0){
    g_Th[growL*HEADS + h] = tL;
    g_Th[growH*HEADS + h] = tH;
  }
}

// t_new
__global__ void tnew_kernel()
{
  int r = blockIdx.x*256 + threadIdx.x;
  if(r >= ROWS) return;
  float s = 0.f;
  #pragma unroll
  for(int h=0; h<HEADS; h++){ float t = g_Th[r*HEADS+h]; s += t*t; }
  splitStore(g_AINh + (size_t)r*KP1, g_AINl + (size_t)r*KP1, sqrtf(s - (float)(HEADS-1)));
}

// time col for mlp hidden
__global__ void time_mlp_kernel()
{
  __shared__ float red[8];
  int row = blockIdx.x, tid = threadIdx.x;
  float s = 0.f;
  #pragma unroll
  for(int q=0;q<12;q++){
    size_t idx = (size_t)row*KP2 + 1 + tid + q*256;
    float x = __bfloat162float(g_H1h[idx]) + __bfloat162float(g_H1l[idx]);
    s += x*x;
  }
  s = blockSum(s, red);
  if(tid==0) splitStore(g_H1h + (size_t)row*KP2, g_H1l + (size_t)row*KP2, sqrtf(1.f + s));
}

// final
__global__ void final_kernel(float* __restrict__ out)
{
  __shared__ float red[8];
  int row = blockIdx.x, tid = threadIdx.x;
  float v[3]; float s = 0.f;
  #pragma unroll
  for(int q=0;q<3;q++){
    int j = tid + q*256;
    float x = g_G2[(size_t)row*D + j] + g_OUT[(size_t)row*D + j];
    v[q] = x; s += x*x;
  }
  s = blockSum(s, red);
  #pragma unroll
  for(int q=0;q<3;q++){
    int j = tid + q*256;
    out[(size_t)row*DH + 1 + j] = v[q];
  }
  if(tid==0) out[(size_t)row*DH] = sqrtf(1.f + s);
}

// ---------------------------------------------------------------------------
// Launch
// ---------------------------------------------------------------------------
extern "C" void kernel_launch(void* const* d_in, const int* in_sizes, int n_in,
                              void* d_out, int out_size)
{
  const float* x    = (const float*)d_in[0];
  const float* Wq   = (const float*)d_in[1];
  const float* Wk   = (const float*)d_in[2];
  const float* Wv   = (const float*)d_in[3];
  const float* Wo   = (const float*)d_in[4];
  const float* ln1g = (const float*)d_in[5];
  const float* ln1b = (const float*)d_in[6];
  const float* ln2g = (const float*)d_in[7];
  const float* ln2b = (const float*)d_in[8];
  const float* Wm1  = (const float*)d_in[9];
  const float* Wm2  = (const float*)d_in[10];
  const float* araw = (const float*)d_in[11];
  const float* traw = (const float*)d_in[12];
  const float* lraw = (const float*)d_in[13];
  float* out = (float*)d_out;

  float *pQKV, *pMO, *pOUT, *pG2;
  cudaGetSymbolAddress((void**)&pQKV, g_QKVf);
  cudaGetSymbolAddress((void**)&pMO,  g_MO);
  cudaGetSymbolAddress((void**)&pOUT, g_OUT);
  cudaGetSymbolAddress((void**)&pG2,  g_G2);

  __nv_bfloat16 *pX1h,*pX1l,*pAINh,*pAINl,*pHh,*pHl,*pH1h,*pH1l;
  __nv_bfloat16 *pWqkvh,*pWqkvl,*pWoh,*pWol,*pW1h,*pW1l,*pW2h,*pW2l;
  cudaGetSymbolAddress((void**)&pX1h,  g_X1h);  cudaGetSymbolAddress((void**)&pX1l,  g_X1l);
  cudaGetSymbolAddress((void**)&pAINh, g_AINh); cudaGetSymbolAddress((void**)&pAINl, g_AINl);
  cudaGetSymbolAddress((void**)&pHh,   g_Hh);   cudaGetSymbolAddress((void**)&pHl,   g_Hl);
  cudaGetSymbolAddress((void**)&pH1h,  g_H1h);  cudaGetSymbolAddress((void**)&pH1l,  g_H1l);
  cudaGetSymbolAddress((void**)&pWqkvh,g_Wqkvh);cudaGetSymbolAddress((void**)&pWqkvl,g_Wqkvl);
  cudaGetSymbolAddress((void**)&pWoh,  g_Woh);  cudaGetSymbolAddress((void**)&pWol,  g_Wol);
  cudaGetSymbolAddress((void**)&pW1h,  g_W1h);  cudaGetSymbolAddress((void**)&pW1l,  g_W1l);
  cudaGetSymbolAddress((void**)&pW2h,  g_W2h);  cudaGetSymbolAddress((void**)&pW2l,  g_W2l);

  cudaFuncSetAttribute(hgemm_kernel, cudaFuncAttributeMaxDynamicSharedMemorySize,
                       HG_SMEM_BYTES);

  // 0. weight split-conversions
  {
    int tq = 3*D*DH;
    convsplit_qkv_kernel<<<(tq+255)/256,256>>>(Wq, Wk, Wv, pWqkvh, pWqkvl);
    int t1 = D*DH;
    convsplit_kernel<<<(t1+255)/256,256>>>(Wo, pWoh, pWol, DH, KP1, t1);
    int t2 = DM*DH;
    convsplit_kernel<<<(t2+255)/256,256>>>(Wm1, pW1h, pW1l, DH, KP1, t2);
    int t3 = D*DMH;
    convsplit_kernel<<<(t3+255)/256,256>>>(Wm2, pW2h, pW2l, DMH, KP2, t3);
  }

  // 1. ln1 + add_time
  ln_addtime_kernel<<<ROWS,256>>>(x, DH, 1, nullptr, 0, 0, ln1g, ln1b, pX1h, pX1l, nullptr);

  // 2. fused QKV projection (N=2304)
  dim3 gqkv(2304/128, ROWS/128);
  hgemm_kernel<<<gqkv,256,HG_SMEM_BYTES>>>(pX1h,pX1l, pWqkvh,pWqkvl, pQKV,nullptr,nullptr, KP1, 0, 1);

  // 3. qt, kt, v_tan + split planes
  prep_kernel<<<(BH*SEQ)/8, 256>>>();

  // 4. tensor-core fused attention
  attn_kernel<<<dim3(SEQ/128, BH), 256>>>(araw, traw, lraw);

  // 5. t_new
  tnew_kernel<<<ROWS/256, 256>>>();

  // 6. Wo projection
  dim3 g768(D/128, ROWS/128);
  hgemm_kernel<<<g768,256,HG_SMEM_BYTES>>>(pAINh,pAINl, pWoh,pWol, pMO,nullptr,nullptr, KP1, D, 0);

  // 7. residual + ln2
  ln_addtime_kernel<<<ROWS,256>>>(pMO, D, 0, x, DH, 1, ln2g, ln2b, pHh, pHl, pOUT);

  // 8. MLP up with gelu
  dim3 g3072(DM/128, ROWS/128);
  hgemm_kernel<<<g3072,256,HG_SMEM_BYTES>>>(pHh,pHl, pW1h,pW1l, nullptr, pH1h+1, pH1l+1, KP1, KP2, 2);

  // 9. mlp hidden time col
  time_mlp_kernel<<<ROWS,256>>>();

  // 10. MLP down
  hgemm_kernel<<<g768,256,HG_SMEM_BYTES>>>(pH1h,pH1l, pW2h,pW2l, pG2,nullptr,nullptr, KP2, D, 0);

  // 11. final
  final_kernel<<<ROWS,256>>>(out);
}

// round 7
// speedup vs baseline: 2.6913x; 1.0379x over previous
#include <cuda_runtime.h>
#include <cuda_bf16.h>
#include <math.h>
#include <cstdint>

// ---------------------------------------------------------------------------
// Problem constants
// ---------------------------------------------------------------------------
#define BATCH 4
#define SEQ   1024
#define D     768
#define DH    769
#define HEADS 12
#define HDIM  64
#define BH    (BATCH*HEADS)      // 48
#define ROWS  (BATCH*SEQ)        // 4096
#define DM    3072
#define DMH   3073
#define KP1   800
#define KP2   3104

// ---------------------------------------------------------------------------
// Scratch
// ---------------------------------------------------------------------------
__device__ float g_QKVf[3*BH*SEQ*HDIM];   // Q | K | V per-head fp32
__device__ float g_qt [BH*SEQ];
__device__ float g_kt [BH*SEQ];
__device__ float g_Th [ROWS*HEADS];
__device__ float g_MO [ROWS*D];
__device__ float g_OUT[ROWS*D];
__device__ float g_G2 [ROWS*D];

// bf16 per-head planes for attention (Q,K single; V split)
__device__ __nv_bfloat16 g_Qsph[BH*SEQ*HDIM];
__device__ __nv_bfloat16 g_Ksph[BH*SEQ*HDIM];
__device__ __nv_bfloat16 g_Vsph[BH*SEQ*HDIM], g_Vspl[BH*SEQ*HDIM];

// split-bf16 activation planes
__device__ __nv_bfloat16 g_X1h [ROWS*KP1], g_X1l [ROWS*KP1];
__device__ __nv_bfloat16 g_AINh[ROWS*KP1], g_AINl[ROWS*KP1];
__device__ __nv_bfloat16 g_Hh  [ROWS*KP1], g_Hl  [ROWS*KP1];
__device__ __nv_bfloat16 g_H1h [ROWS*KP2], g_H1l [ROWS*KP2];

// split-bf16 weight planes
__device__ __nv_bfloat16 g_Wqkvh[3*D*KP1], g_Wqkvl[3*D*KP1];
__device__ __nv_bfloat16 g_Woh[D*KP1],  g_Wol[D*KP1];
__device__ __nv_bfloat16 g_W1h[DM*KP1], g_W1l[DM*KP1];
__device__ __nv_bfloat16 g_W2h[D*KP2],  g_W2l[D*KP2];

// ---------------------------------------------------------------------------
// Helpers
// ---------------------------------------------------------------------------
__device__ __forceinline__ float warpSum(float v){
  #pragma unroll
  for(int o=16;o>0;o>>=1) v += __shfl_xor_sync(0xffffffffu, v, o);
  return v;
}
__device__ __forceinline__ float blockSum(float v, float* sh){
  int lane = threadIdx.x & 31, w = threadIdx.x >> 5;
  v = warpSum(v);
  if(lane==0) sh[w] = v;
  __syncthreads();
  float r = (threadIdx.x < 8) ? sh[threadIdx.x] : 0.f;
  if(w==0) r = warpSum(r);
  if(threadIdx.x==0) sh[0] = r;
  __syncthreads();
  r = sh[0];
  __syncthreads();
  return r;
}
__device__ __forceinline__ void splitStore(__nv_bfloat16* ph, __nv_bfloat16* pl, float x){
  __nv_bfloat16 h = __float2bfloat16(x);
  *ph = h;
  *pl = __float2bfloat16(x - __bfloat162float(h));
}
__device__ __forceinline__ void packhi(float a, float b, unsigned &h){
  __nv_bfloat162 hp; hp.x = __float2bfloat16(a); hp.y = __float2bfloat16(b);
  h = *(unsigned*)&hp;
}
__device__ __forceinline__ void cpasync16(void* s, const void* g){
  unsigned int sa = (unsigned int)__cvta_generic_to_shared(s);
  asm volatile("cp.async.cg.shared.global [%0], [%1], 16;\n" :: "r"(sa), "l"(g));
}
#define CP_COMMIT asm volatile("cp.async.commit_group;\n")
#define CP_WAIT(n) asm volatile("cp.async.wait_group %0;\n" :: "n"(n))

__device__ __forceinline__ void mma16816(float* d, const unsigned* a, const unsigned* b){
  asm volatile("mma.sync.aligned.m16n8k16.row.col.f32.bf16.bf16.f32 "
    "{%0,%1,%2,%3},{%4,%5,%6,%7},{%8,%9},{%0,%1,%2,%3};"
    : "+f"(d[0]),"+f"(d[1]),"+f"(d[2]),"+f"(d[3])
    : "r"(a[0]),"r"(a[1]),"r"(a[2]),"r"(a[3]),"r"(b[0]),"r"(b[1]));
}
__device__ __forceinline__ void ldsm4(unsigned* r, unsigned addr){
  asm volatile("ldmatrix.sync.aligned.m8n8.x4.shared.b16 {%0,%1,%2,%3}, [%4];"
    : "=r"(r[0]),"=r"(r[1]),"=r"(r[2]),"=r"(r[3]) : "r"(addr));
}

// ---------------------------------------------------------------------------
// Weight split-converts
// ---------------------------------------------------------------------------
__global__ void convsplit_kernel(const float* __restrict__ W,
                                 __nv_bfloat16* __restrict__ Wh,
                                 __nv_bfloat16* __restrict__ Wl,
                                 int Kk, int KPp, int total)
{
  int i = blockIdx.x*256 + threadIdx.x;
  if(i >= total) return;
  int r = i / Kk, c = i - r*Kk;
  float x = W[i];
  __nv_bfloat16 h = __float2bfloat16(x);
  Wh[(size_t)r*KPp + c] = h;
  Wl[(size_t)r*KPp + c] = __float2bfloat16(x - __bfloat162float(h));
}

__global__ void convsplit_qkv_kernel(const float* __restrict__ Wq,
                                     const float* __restrict__ Wk,
                                     const float* __restrict__ Wv,
                                     __nv_bfloat16* __restrict__ Wh,
                                     __nv_bfloat16* __restrict__ Wl)
{
  int i = blockIdx.x*256 + threadIdx.x;
  if(i >= 3*D*DH) return;
  int r = i / DH, c = i - r*DH;
  const float* src = (r < D) ? Wq : ((r < 2*D) ? Wk : Wv);
  int rl = (r < D) ? r : ((r < 2*D) ? r - D : r - 2*D);
  float x = src[(size_t)rl*DH + c];
  __nv_bfloat16 h = __float2bfloat16(x);
  Wh[(size_t)r*KP1 + c] = h;
  Wl[(size_t)r*KP1 + c] = __float2bfloat16(x - __bfloat162float(h));
}

// ---------------------------------------------------------------------------
// LayerNorm (+optional add) + add_time -> split planes
// ---------------------------------------------------------------------------
__global__ void ln_addtime_kernel(const float* __restrict__ in1, int ld1, int off1,
                                  const float* __restrict__ in2, int ld2, int off2,
                                  const float* __restrict__ gv, const float* __restrict__ bv,
                                  __nv_bfloat16* __restrict__ outh,
                                  __nv_bfloat16* __restrict__ outl,
                                  float* __restrict__ rawOut)
{
  __shared__ float red[8];
  int row = blockIdx.x, tid = threadIdx.x;
  float v[3];
  #pragma unroll
  for(int q=0;q<3;q++){
    int j = tid + q*256;
    float x = in1[(size_t)row*ld1 + off1 + j];
    if(in2) x += in2[(size_t)row*ld2 + off2 + j];
    v[q] = x;
    if(rawOut) rawOut[(size_t)row*D + j] = x;
  }
  float s  = v[0]+v[1]+v[2];
  float s2 = v[0]*v[0]+v[1]*v[1]+v[2]*v[2];
  s  = blockSum(s,  red);
  float mu = s * (1.f/768.f);
  s2 = blockSum(s2, red);
  float var = s2*(1.f/768.f) - mu*mu;
  float rstd = rsqrtf(var + 1e-5f);
  float w[3]; float n2 = 0.f;
  #pragma unroll
  for(int q=0;q<3;q++){
    int j = tid + q*256;
    w[q] = (v[q]-mu)*rstd*gv[j] + bv[j];
    n2 += w[q]*w[q];
  }
  n2 = blockSum(n2, red);
  #pragma unroll
  for(int q=0;q<3;q++){
    int j = tid + q*256;
    splitStore(outh + (size_t)row*KP1 + 1 + j, outl + (size_t)row*KP1 + 1 + j, w[q]);
  }
  if(tid==0) splitStore(outh + (size_t)row*KP1, outl + (size_t)row*KP1, sqrtf(1.f + n2));
}

// ---------------------------------------------------------------------------
// Tensor-core split-bf16 GEMM: C[M,N] = A[M,K]*B[N,K]^T
//   128x128 CTA tile, BK=32, 8 warps, 64x32 warp tile,
//   3-stage cp.async pipeline, single __syncthreads per iter, ldmatrix frags.
//   mode 0: fp32 out (ldc); 1: fused-QKV head-scatter; 2: gelu + split out.
// ---------------------------------------------------------------------------
#define HG_STAGE_BF16 20480
#define HG_STAGE_BYTES 40960
#define HG_SMEM_BYTES (3*HG_STAGE_BYTES)

__global__ void __launch_bounds__(256,1) hgemm_kernel(
    const __nv_bfloat16* __restrict__ Ah, const __nv_bfloat16* __restrict__ Al,
    const __nv_bfloat16* __restrict__ Bh, const __nv_bfloat16* __restrict__ Bl,
    float* __restrict__ Cf, __nv_bfloat16* __restrict__ Ch, __nv_bfloat16* __restrict__ Cl,
    int KP, int ldc, int mode)
{
  extern __shared__ __nv_bfloat16 smb[];
  int tid = threadIdx.x;
  int lane = tid & 31, wid = tid >> 5;
  int wm = wid >> 2, wn = wid & 3;
  int g = lane >> 2, t = lane & 3;
  int row0 = blockIdx.y*128, col0 = blockIdx.x*128;

  float acc[4][4][4];
  #pragma unroll
  for(int mi=0;mi<4;mi++)
    #pragma unroll
    for(int ni=0;ni<4;ni++)
      #pragma unroll
      for(int e=0;e<4;e++) acc[mi][ni][e]=0.f;

  const int niter = KP >> 5;
  const unsigned smemU = (unsigned)__cvta_generic_to_shared(smb);

  // A ldmatrix address (per mi, per plane): rows 16 x k16 tiles
  const int aRow = wm*64 + (lane&7) + ((lane>>3)&1)*8;
  const int aCol = ((lane>>4)&1)*8;
  const unsigned aOffH = (unsigned)((aRow*40 + aCol)*2);
  // B ldmatrix x4 straddling hi/lo planes:
  //   octets 0,1 -> Bh (k0,k8); octets 2,3 -> Bl (k0,k8)
  const int bRow8 = lane & 7;
  const int bSel  = (lane >> 3) & 1;
  const unsigned bOff4 = (unsigned)(20480 + ((bRow8)*40 + bSel*8)*2 + ((lane & 16) ? 10240 : 0));

  // stage loader
  int ldrow = tid >> 2, ldcc = (tid & 3)*8;
  int ldrow2 = (tid+256) >> 2, ldcc2 = ((tid+256) & 3)*8;

  #define LOAD_STAGE(stg, k0) do{                                             \
    __nv_bfloat16* s = smb + (stg)*HG_STAGE_BF16;                             \
    cpasync16(s +          ldrow*40 + ldcc,  Ah + (size_t)(row0+ldrow)*KP + (k0) + ldcc);  \
    cpasync16(s +  5120 +  ldrow*40 + ldcc,  Al + (size_t)(row0+ldrow)*KP + (k0) + ldcc);  \
    cpasync16(s + 10240 +  ldrow*40 + ldcc,  Bh + (size_t)(col0+ldrow)*KP + (k0) + ldcc);  \
    cpasync16(s + 15360 +  ldrow*40 + ldcc,  Bl + (size_t)(col0+ldrow)*KP + (k0) + ldcc);  \
    cpasync16(s +          ldrow2*40 + ldcc2, Ah + (size_t)(row0+ldrow2)*KP + (k0) + ldcc2);\
    cpasync16(s +  5120 +  ldrow2*40 + ldcc2, Al + (size_t)(row0+ldrow2)*KP + (k0) + ldcc2);\
    cpasync16(s + 10240 +  ldrow2*40 + ldcc2, Bh + (size_t)(col0+ldrow2)*KP + (k0) + ldcc2);\
    cpasync16(s + 15360 +  ldrow2*40 + ldcc2, Bl + (size_t)(col0+ldrow2)*KP + (k0) + ldcc2);\
    CP_COMMIT;                                                                \
  } while(0)

  LOAD_STAGE(0, 0);
  LOAD_STAGE(1, 32);

  for(int it=0; it<niter; it++){
    if(it == niter-1){ CP_WAIT(0); } else { CP_WAIT(1); }
    __syncthreads();
    if(it+2 < niter) LOAD_STAGE((it+2)%3, (it+2)<<5);

    const unsigned sb = smemU + (unsigned)((it%3)*HG_STAGE_BYTES);

    #pragma unroll
    for(int ks=0;ks<2;ks++){
      unsigned a_h[4][4], a_l[4][4];
      #pragma unroll
      for(int mi=0;mi<4;mi++){
        unsigned ad = sb + aOffH + (unsigned)(mi*1280 + ks*32);
        ldsm4(a_h[mi], ad);
        ldsm4(a_l[mi], ad + 10240);
      }
      unsigned bhl[4][4];   // per ni: {bh0,bh1,bl0,bl1}
      #pragma unroll
      for(int ni=0;ni<4;ni++){
        unsigned bd = sb + bOff4 + (unsigned)(wn*2560 + ni*640 + ks*32);
        ldsm4(bhl[ni], bd);
      }
      #pragma unroll
      for(int mi=0;mi<4;mi++)
        #pragma unroll
        for(int ni=0;ni<4;ni++) mma16816(acc[mi][ni], a_h[mi], bhl[ni]);
      #pragma unroll
      for(int mi=0;mi<4;mi++)
        #pragma unroll
        for(int ni=0;ni<4;ni++) mma16816(acc[mi][ni], a_h[mi], bhl[ni]+2);
      #pragma unroll
      for(int mi=0;mi<4;mi++)
        #pragma unroll
        for(int ni=0;ni<4;ni++) mma16816(acc[mi][ni], a_l[mi], bhl[ni]);
    }
  }

  // ---- epilogue ----
  int mat = blockIdx.x / 6;
  int cmatBase = mat*768;
  #pragma unroll
  for(int mi=0;mi<4;mi++){
    int rb = row0 + wm*64 + mi*16 + g;
    #pragma unroll
    for(int ni=0;ni<4;ni++){
      int cb = col0 + wn*32 + ni*8 + 2*t;
      float* a = acc[mi][ni];
      #pragma unroll
      for(int e=0;e<4;e++){
        int r = rb + (e>=2 ? 8 : 0);
        int c = cb + (e&1);
        float v = a[e];
        if(mode==2){
          v = 0.5f*v*(1.f + erff(v*0.70710678118654752f));
          splitStore(Ch + (size_t)r*ldc + c, Cl + (size_t)r*ldc + c, v);
        } else if(mode==1){
          int b_ = r >> 10, ii = r & 1023;
          int cmat = c - cmatBase;
          int h = cmat >> 6, cc2 = cmat & 63;
          Cf[(size_t)mat*(BH*SEQ*HDIM) + (size_t)(((b_*HEADS+h)<<10) + ii)*HDIM + cc2] = v;
        } else {
          Cf[(size_t)r*ldc + c] = v;
        }
      }
    }
  }
}

// ---------------------------------------------------------------------------
// Prep: qt, kt, v->v_tan; Q,K single bf16 planes; V split planes.
// ---------------------------------------------------------------------------
__global__ void prep_kernel()
{
  int w = blockIdx.x*8 + (threadIdx.x>>5);
  int lane = threadIdx.x & 31;

  const float* q = g_QKVf + (size_t)w*HDIM;
  float qv[2]; float s = 0.f;
  #pragma unroll
  for(int e=0;e<2;e++){ qv[e] = q[lane+32*e]; s += qv[e]*qv[e]; }
  s = warpSum(s);
  if(lane==0) g_qt[w] = sqrtf(1.f + s);
  #pragma unroll
  for(int e=0;e<2;e++)
    g_Qsph[(size_t)w*HDIM + lane+32*e] = __float2bfloat16(qv[e]);

  const float* k = g_QKVf + (size_t)(BH*SEQ)*HDIM + (size_t)w*HDIM;
  float kv[2]; s = 0.f;
  #pragma unroll
  for(int e=0;e<2;e++){ kv[e] = k[lane+32*e]; s += kv[e]*kv[e]; }
  s = warpSum(s);
  if(lane==0) g_kt[w] = sqrtf(1.f + s);
  #pragma unroll
  for(int e=0;e<2;e++)
    g_Ksph[(size_t)w*HDIM + lane+32*e] = __float2bfloat16(kv[e]);

  const float* v = g_QKVf + (size_t)(2*BH*SEQ)*HDIM + (size_t)w*HDIM;
  float vv[2]; s = 0.f;
  #pragma unroll
  for(int e=0;e<2;e++){ vv[e] = v[lane+32*e]; s += vv[e]*vv[e]; }
  s = warpSum(s);
  float sn = sqrtf(s);
  float vt = sqrtf(1.f + s);
  float vc = fmaxf(vt, 1.0000001f);
  float dist = __logf(vc + sqrtf((vc-1.f)*(vc+1.f)));
  float scl = dist / fmaxf(sn, 1e-8f);
  #pragma unroll
  for(int e=0;e<2;e++)
    splitStore(g_Vsph + (size_t)w*HDIM + lane+32*e, g_Vspl + (size_t)w*HDIM + lane+32*e, vv[e]*scl);
}

// ---------------------------------------------------------------------------
// Tensor-core fused hyperbolic flash attention.
//   QK^T: 1-term bf16. P.V: 2-term (P single, V split).
// ---------------------------------------------------------------------------
#define AT_STR   72
#define AT_USTR  36

__device__ __forceinline__ float attn_logit(float sv, float qt, float cq, float rsh,
                                            float Bq, float ktj, float lam, float tau,
                                            float spm){
  float rawc = fmaxf(qt*ktj - sv, 1.0f);
  bool selfp = rawc < 1.00001f;
  float c = selfp ? 2.f : rawc;
  float x = (c-1.f)*(c+1.f);
  float rs = rsqrtf(fmaxf(x, 1e-12f));
  float sh = x*rs;
  float dist = __logf(c + sh);
  float ck = fmaxf(ktj, 1.0000001f);
  float Z = (rawc*cq - ck)*rs*rsh;
  Z = selfp ? 1.f : fminf(fmaxf(Z, -1.f), 1.f);
  float pen = -lam*__logf(1.f + dist*dist);
  float ent = __logf(1.f + __expf(Bq + Z - 0.1f)) - spm;
  return pen - tau*ent;
}

__global__ void __launch_bounds__(256,1) attn_kernel(
    const float* __restrict__ alpha_raw,
    const float* __restrict__ tau_raw,
    const float* __restrict__ lambda_raw)
{
  __shared__ __nv_bfloat16 smK[3*64*AT_STR];   // K | VTh | VTl (Q staging reuses)
  __shared__ float kts[64];

  const int bh = blockIdx.y;
  const int qrow0 = blockIdx.x*128;
  const int tid = threadIdx.x;
  const int lane = tid & 31, wid = tid >> 5;
  const int g = lane >> 2, t = lane & 3;

  __nv_bfloat16* Khs = smK;
  __nv_bfloat16* VThs= smK + 64*AT_STR;
  __nv_bfloat16* VTls= smK + 2*64*AT_STR;

  const float alpha = log1pf(expf(alpha_raw[0]));
  const float tau   = log1pf(expf(tau_raw[0]));
  const float lam   = log1pf(expf(lambda_raw[0]));
  const float spm   = log1pf(expf(-0.1f));

  // ---- stage Q (single plane) into smem, extract fragments ----
  {
    const __nv_bfloat16* gQh = g_Qsph + ((size_t)bh*SEQ + qrow0)*HDIM;
    #pragma unroll
    for(int itn=0; itn<4; itn++){
      int ch = tid + itn*256;
      int r = ch >> 3, c0 = (ch & 7)*8;
      *(uint4*)(smK + r*AT_STR + c0) = *(const uint4*)(gQh + r*HDIM + c0);
    }
  }
  __syncthreads();

  unsigned qh[4][4];
  {
    const unsigned* pQh = (const unsigned*)smK;
    int rbase = wid*16 + g;
    #pragma unroll
    for(int ks=0; ks<4; ks++){
      int base = rbase*AT_USTR + ks*8 + t;
      qh[ks][0]=pQh[base];               qh[ks][1]=pQh[base+8*AT_USTR];
      qh[ks][2]=pQh[base+4];             qh[ks][3]=pQh[base+8*AT_USTR+4];
    }
  }

  const int rowL = qrow0 + wid*16 + g;
  const int rowH = rowL + 8;
  float qtL = g_qt[bh*SEQ + rowL], qtH = g_qt[bh*SEQ + rowH];
  float cqL = fmaxf(qtL, 1.0000001f), cqH = fmaxf(qtH, 1.0000001f);
  float ctL = fminf(__logf(cqL + sqrtf((cqL-1.f)*(cqL+1.f))), 40.f);
  float ctH = fminf(__logf(cqH + sqrtf((cqH-1.f)*(cqH+1.f))), 40.f);
  float rshL = 1.f/sinhf(ctL), rshH = 1.f/sinhf(ctH);
  float BqL = alpha*ctL/(1.f + alpha*ctL);
  float BqH = alpha*ctH/(1.f + alpha*ctH);

  float accO[8][4];
  #pragma unroll
  for(int ni=0;ni<8;ni++)
    #pragma unroll
    for(int e=0;e<4;e++) accO[ni][e]=0.f;
  float lsumL = 0.f, lsumH = 0.f;

  const __nv_bfloat16* gKh = g_Ksph + (size_t)bh*SEQ*HDIM;
  const __nv_bfloat16* gVh = g_Vsph + (size_t)bh*SEQ*HDIM;
  const __nv_bfloat16* gVl = g_Vspl + (size_t)bh*SEQ*HDIM;
  const float* gkt = g_kt + bh*SEQ;

  for(int jt=0; jt<16; jt++){
    const int jbase = jt*64;
    __syncthreads();
    // load K direct (512 chunks over 2 iters), V transposed (2 planes)
    #pragma unroll
    for(int itn=0; itn<2; itn++){
      int ch = tid + itn*256;
      int j = ch >> 3, c0 = (ch & 7)*8;
      *(uint4*)(Khs + j*AT_STR + c0) = *(const uint4*)(gKh + (size_t)(jbase+j)*HDIM + c0);
      uint4 vh = *(const uint4*)(gVh + (size_t)(jbase+j)*HDIM + c0);
      uint4 vl = *(const uint4*)(gVl + (size_t)(jbase+j)*HDIM + c0);
      const __nv_bfloat16* vhp = (const __nv_bfloat16*)&vh;
      const __nv_bfloat16* vlp = (const __nv_bfloat16*)&vl;
      #pragma unroll
      for(int e=0;e<8;e++){
        VThs[(c0+e)*AT_STR + j] = vhp[e];
        VTls[(c0+e)*AT_STR + j] = vlp[e];
      }
    }
    if(tid < 64) kts[tid] = gkt[jbase + tid];
    __syncthreads();

    // ---- S = Q.K^T (1-term) ----
    float accS[8][4];
    #pragma unroll
    for(int ni=0;ni<8;ni++)
      #pragma unroll
      for(int e=0;e<4;e++) accS[ni][e]=0.f;

    const unsigned* pKh = (const unsigned*)Khs;
    #pragma unroll
    for(int ks=0; ks<4; ks++){
      #pragma unroll
      for(int ni=0; ni<8; ni++){
        int base = (ni*8+g)*AT_USTR + ks*8 + t;
        unsigned bhf[2] = { pKh[base], pKh[base+4] };
        mma16816(accS[ni], qh[ks], bhf);
      }
    }

    // ---- logits + exp (fixed max 0) ----
    #pragma unroll
    for(int ni=0; ni<8; ni++){
      float2 ktp = *(const float2*)&kts[ni*8 + 2*t];
      float z0 = attn_logit(accS[ni][0], qtL, cqL, rshL, BqL, ktp.x, lam, tau, spm);
      float z1 = attn_logit(accS[ni][1], qtL, cqL, rshL, BqL, ktp.y, lam, tau, spm);
      float z2 = attn_logit(accS[ni][2], qtH, cqH, rshH, BqH, ktp.x, lam, tau, spm);
      float z3 = attn_logit(accS[ni][3], qtH, cqH, rshH, BqH, ktp.y, lam, tau, spm);
      float p0 = __expf(z0), p1 = __expf(z1), p2 = __expf(z2), p3 = __expf(z3);
      lsumL += p0 + p1;
      lsumH += p2 + p3;
      accS[ni][0]=p0; accS[ni][1]=p1; accS[ni][2]=p2; accS[ni][3]=p3;
    }

    // ---- O += P.V (2-term: P single, V split) ----
    const unsigned* pVh = (const unsigned*)VThs;
    const unsigned* pVl = (const unsigned*)VTls;
    #pragma unroll
    for(int kc=0; kc<4; kc++){
      unsigned aP[4];
      packhi(accS[2*kc  ][0], accS[2*kc  ][1], aP[0]);
      packhi(accS[2*kc  ][2], accS[2*kc  ][3], aP[1]);
      packhi(accS[2*kc+1][0], accS[2*kc+1][1], aP[2]);
      packhi(accS[2*kc+1][2], accS[2*kc+1][3], aP[3]);
      #pragma unroll
      for(int ni=0; ni<8; ni++){
        int base = (ni*8+g)*AT_USTR + kc*8 + t;
        unsigned bhf[2] = { pVh[base], pVh[base+4] };
        unsigned blf[2] = { pVl[base], pVl[base+4] };
        mma16816(accO[ni], aP, bhf);
        mma16816(accO[ni], aP, blf);
      }
    }
  }

  // ---- epilogue ----
  float lL = lsumL, lH = lsumH;
  #pragma unroll
  for(int o=1;o<4;o<<=1){
    lL += __shfl_xor_sync(0xffffffffu, lL, o);
    lH += __shfl_xor_sync(0xffffffffu, lH, o);
  }
  float invL = 1.f/(lL*(1.f + 1e-8f));
  float invH = 1.f/(lH*(1.f + 1e-8f));

  float agL[8][2], agH[8][2];
  float nnL = 0.f, nnH = 0.f;
  #pragma unroll
  for(int ni=0;ni<8;ni++){
    agL[ni][0] = accO[ni][0]*invL; agL[ni][1] = accO[ni][1]*invL;
    agH[ni][0] = accO[ni][2]*invH; agH[ni][1] = accO[ni][3]*invH;
    nnL += agL[ni][0]*agL[ni][0] + agL[ni][1]*agL[ni][1];
    nnH += agH[ni][0]*agH[ni][0] + agH[ni][1]*agH[ni][1];
  }
  #pragma unroll
  for(int o=1;o<4;o<<=1){
    nnL += __shfl_xor_sync(0xffffffffu, nnL, o);
    nnH += __shfl_xor_sync(0xffffffffu, nnH, o);
  }
  nnL = sqrtf(nnL); nnH = sqrtf(nnH);
  float tL = coshf(nnL), tH = coshf(nnH);
  float sclL = sinhf(nnL)/fmaxf(nnL, 1e-8f);
  float sclH = sinhf(nnH)/fmaxf(nnH, 1e-8f);

  const int b_ = bh / HEADS, h = bh % HEADS;
  const int growL = b_*SEQ + rowL, growH = b_*SEQ + rowH;
  #pragma unroll
  for(int ni=0;ni<8;ni++){
    int c0 = ni*8 + 2*t;
    size_t iL = (size_t)growL*KP1 + 1 + h*HDIM + c0;
    size_t iH = (size_t)growH*KP1 + 1 + h*HDIM + c0;
    splitStore(g_AINh + iL,     g_AINl + iL,     agL[ni][0]*sclL);
    splitStore(g_AINh + iL + 1, g_AINl + iL + 1, agL[ni][1]*sclL);
    splitStore(g_AINh + iH,     g_AINl + iH,     agH[ni][0]*sclH);
    splitStore(g_AINh + iH + 1, g_AINl + iH + 1, agH[ni][1]*sclH);
  }
  if(t==0){
    g_Th[growL*HEADS + h] = tL;
    g_Th[growH*HEADS + h] = tH;
  }
}

// t_new
__global__ void tnew_kernel()
{
  int r = blockIdx.x*256 + threadIdx.x;
  if(r >= ROWS) return;
  float s = 0.f;
  #pragma unroll
  for(int h=0; h<HEADS; h++){ float t = g_Th[r*HEADS+h]; s += t*t; }
  splitStore(g_AINh + (size_t)r*KP1, g_AINl + (size_t)r*KP1, sqrtf(s - (float)(HEADS-1)));
}

// time col for mlp hidden
__global__ void time_mlp_kernel()
{
  __shared__ float red[8];
  int row = blockIdx.x, tid = threadIdx.x;
  float s = 0.f;
  #pragma unroll
  for(int q=0;q<12;q++){
    size_t idx = (size_t)row*KP2 + 1 + tid + q*256;
    float x = __bfloat162float(g_H1h[idx]) + __bfloat162float(g_H1l[idx]);
    s += x*x;
  }
  s = blockSum(s, red);
  if(tid==0) splitStore(g_H1h + (size_t)row*KP2, g_H1l + (size_t)row*KP2, sqrtf(1.f + s));
}

// final
__global__ void final_kernel(float* __restrict__ out)
{
  __shared__ float red[8];
  int row = blockIdx.x, tid = threadIdx.x;
  float v[3]; float s = 0.f;
  #pragma unroll
  for(int q=0;q<3;q++){
    int j = tid + q*256;
    float x = g_G2[(size_t)row*D + j] + g_OUT[(size_t)row*D + j];
    v[q] = x; s += x*x;
  }
  s = blockSum(s, red);
  #pragma unroll
  for(int q=0;q<3;q++){
    int j = tid + q*256;
    out[(size_t)row*DH + 1 + j] = v[q];
  }
  if(tid==0) out[(size_t)row*DH] = sqrtf(1.f + s);
}

// ---------------------------------------------------------------------------
// Launch
// ---------------------------------------------------------------------------
extern "C" void kernel_launch(void* const* d_in, const int* in_sizes, int n_in,
                              void* d_out, int out_size)
{
  const float* x    = (const float*)d_in[0];
  const float* Wq   = (const float*)d_in[1];
  const float* Wk   = (const float*)d_in[2];
  const float* Wv   = (const float*)d_in[3];
  const float* Wo   = (const float*)d_in[4];
  const float* ln1g = (const float*)d_in[5];
  const float* ln1b = (const float*)d_in[6];
  const float* ln2g = (const float*)d_in[7];
  const float* ln2b = (const float*)d_in[8];
  const float* Wm1  = (const float*)d_in[9];
  const float* Wm2  = (const float*)d_in[10];
  const float* araw = (const float*)d_in[11];
  const float* traw = (const float*)d_in[12];
  const float* lraw = (const float*)d_in[13];
  float* out = (float*)d_out;

  float *pQKV, *pMO, *pOUT, *pG2;
  cudaGetSymbolAddress((void**)&pQKV, g_QKVf);
  cudaGetSymbolAddress((void**)&pMO,  g_MO);
  cudaGetSymbolAddress((void**)&pOUT, g_OUT);
  cudaGetSymbolAddress((void**)&pG2,  g_G2);

  __nv_bfloat16 *pX1h,*pX1l,*pAINh,*pAINl,*pHh,*pHl,*pH1h,*pH1l;
  __nv_bfloat16 *pWqkvh,*pWqkvl,*pWoh,*pWol,*pW1h,*pW1l,*pW2h,*pW2l;
  cudaGetSymbolAddress((void**)&pX1h,  g_X1h);  cudaGetSymbolAddress((void**)&pX1l,  g_X1l);
  cudaGetSymbolAddress((void**)&pAINh, g_AINh); cudaGetSymbolAddress((void**)&pAINl, g_AINl);
  cudaGetSymbolAddress((void**)&pHh,   g_Hh);   cudaGetSymbolAddress((void**)&pHl,   g_Hl);
  cudaGetSymbolAddress((void**)&pH1h,  g_H1h);  cudaGetSymbolAddress((void**)&pH1l,  g_H1l);
  cudaGetSymbolAddress((void**)&pWqkvh,g_Wqkvh);cudaGetSymbolAddress((void**)&pWqkvl,g_Wqkvl);
  cudaGetSymbolAddress((void**)&pWoh,  g_Woh);  cudaGetSymbolAddress((void**)&pWol,  g_Wol);
  cudaGetSymbolAddress((void**)&pW1h,  g_W1h);  cudaGetSymbolAddress((void**)&pW1l,  g_W1l);
  cudaGetSymbolAddress((void**)&pW2h,  g_W2h);  cudaGetSymbolAddress((void**)&pW2l,  g_W2l);

  cudaFuncSetAttribute(hgemm_kernel, cudaFuncAttributeMaxDynamicSharedMemorySize,
                       HG_SMEM_BYTES);

  // 0. weight split-conversions
  {
    int tq = 3*D*DH;
    convsplit_qkv_kernel<<<(tq+255)/256,256>>>(Wq, Wk, Wv, pWqkvh, pWqkvl);
    int t1 = D*DH;
    convsplit_kernel<<<(t1+255)/256,256>>>(Wo, pWoh, pWol, DH, KP1, t1);
    int t2 = DM*DH;
    convsplit_kernel<<<(t2+255)/256,256>>>(Wm1, pW1h, pW1l, DH, KP1, t2);
    int t3 = D*DMH;
    convsplit_kernel<<<(t3+255)/256,256>>>(Wm2, pW2h, pW2l, DMH, KP2, t3);
  }

  // 1. ln1 + add_time
  ln_addtime_kernel<<<ROWS,256>>>(x, DH, 1, nullptr, 0, 0, ln1g, ln1b, pX1h, pX1l, nullptr);

  // 2. fused QKV projection (N=2304)
  dim3 gqkv(2304/128, ROWS/128);
  hgemm_kernel<<<gqkv,256,HG_SMEM_BYTES>>>(pX1h,pX1l, pWqkvh,pWqkvl, pQKV,nullptr,nullptr, KP1, 0, 1);

  // 3. qt, kt, v_tan + attention planes
  prep_kernel<<<(BH*SEQ)/8, 256>>>();

  // 4. tensor-core fused attention
  attn_kernel<<<dim3(SEQ/128, BH), 256>>>(araw, traw, lraw);

  // 5. t_new
  tnew_kernel<<<ROWS/256, 256>>>();

  // 6. Wo projection
  dim3 g768(D/128, ROWS/128);
  hgemm_kernel<<<g768,256,HG_SMEM_BYTES>>>(pAINh,pAINl, pWoh,pWol, pMO,nullptr,nullptr, KP1, D, 0);

  // 7. residual + ln2
  ln_addtime_kernel<<<ROWS,256>>>(pMO, D, 0, x, DH, 1, ln2g, ln2b, pHh, pHl, pOUT);

  // 8. MLP up with gelu
  dim3 g3072(DM/128, ROWS/128);
  hgemm_kernel<<<g3072,256,HG_SMEM_BYTES>>>(pHh,pHl, pW1h,pW1l, nullptr, pH1h+1, pH1l+1, KP1, KP2, 2);

  // 9. mlp hidden time col
  time_mlp_kernel<<<ROWS,256>>>();

  // 10. MLP down
  hgemm_kernel<<<g768,256,HG_SMEM_BYTES>>>(pH1h,pH1l, pW2h,pW2l, pG2,nullptr,nullptr, KP2, D, 0);

  // 11. final
  final_kernel<<<ROWS,256>>>(out);
}

// round 8
// speedup vs baseline: 2.8730x; 1.0675x over previous
#include <cuda_runtime.h>
#include <cuda_bf16.h>
#include <math.h>
#include <cstdint>

// ---------------------------------------------------------------------------
// Problem constants
// ---------------------------------------------------------------------------
#define BATCH 4
#define SEQ   1024
#define D     768
#define DH    769
#define HEADS 12
#define HDIM  64
#define BH    (BATCH*HEADS)      // 48
#define ROWS  (BATCH*SEQ)        // 4096
#define DM    3072
#define DMH   3073
#define KP1   800
#define KP2   3104

// ---------------------------------------------------------------------------
// Scratch
// ---------------------------------------------------------------------------
__device__ float g_QKVf[3*BH*SEQ*HDIM];   // Q | K | V per-head fp32
__device__ float g_qt [BH*SEQ];
__device__ float g_kt [BH*SEQ];
__device__ float g_Th [ROWS*HEADS];
__device__ float g_MO [ROWS*D];
__device__ float g_OUT[ROWS*D];
__device__ float g_G2 [ROWS*D];

// bf16 per-head planes for attention (Q,K single; V split)
__device__ __nv_bfloat16 g_Qsph[BH*SEQ*HDIM];
__device__ __nv_bfloat16 g_Ksph[BH*SEQ*HDIM];
__device__ __nv_bfloat16 g_Vsph[BH*SEQ*HDIM], g_Vspl[BH*SEQ*HDIM];

// split-bf16 activation planes
__device__ __nv_bfloat16 g_X1h [ROWS*KP1], g_X1l [ROWS*KP1];
__device__ __nv_bfloat16 g_AINh[ROWS*KP1], g_AINl[ROWS*KP1];
__device__ __nv_bfloat16 g_Hh  [ROWS*KP1], g_Hl  [ROWS*KP1];
__device__ __nv_bfloat16 g_H1h [ROWS*KP2], g_H1l [ROWS*KP2];

// split-bf16 weight planes
__device__ __nv_bfloat16 g_Wqkvh[3*D*KP1], g_Wqkvl[3*D*KP1];
__device__ __nv_bfloat16 g_Woh[D*KP1],  g_Wol[D*KP1];
__device__ __nv_bfloat16 g_W1h[DM*KP1], g_W1l[DM*KP1];
__device__ __nv_bfloat16 g_W2h[D*KP2],  g_W2l[D*KP2];

// ---------------------------------------------------------------------------
// Helpers
// ---------------------------------------------------------------------------
__device__ __forceinline__ float warpSum(float v){
  #pragma unroll
  for(int o=16;o>0;o>>=1) v += __shfl_xor_sync(0xffffffffu, v, o);
  return v;
}
__device__ __forceinline__ float blockSum(float v, float* sh){
  int lane = threadIdx.x & 31, w = threadIdx.x >> 5;
  v = warpSum(v);
  if(lane==0) sh[w] = v;
  __syncthreads();
  float r = (threadIdx.x < 8) ? sh[threadIdx.x] : 0.f;
  if(w==0) r = warpSum(r);
  if(threadIdx.x==0) sh[0] = r;
  __syncthreads();
  r = sh[0];
  __syncthreads();
  return r;
}
__device__ __forceinline__ void splitStore(__nv_bfloat16* ph, __nv_bfloat16* pl, float x){
  __nv_bfloat16 h = __float2bfloat16(x);
  *ph = h;
  *pl = __float2bfloat16(x - __bfloat162float(h));
}
__device__ __forceinline__ void packhi(float a, float b, unsigned &h){
  __nv_bfloat162 hp; hp.x = __float2bfloat16(a); hp.y = __float2bfloat16(b);
  h = *(unsigned*)&hp;
}
__device__ __forceinline__ void cpasync16(void* s, const void* g){
  unsigned int sa = (unsigned int)__cvta_generic_to_shared(s);
  asm volatile("cp.async.cg.shared.global [%0], [%1], 16;\n" :: "r"(sa), "l"(g));
}
#define CP_COMMIT asm volatile("cp.async.commit_group;\n")
#define CP_WAIT(n) asm volatile("cp.async.wait_group %0;\n" :: "n"(n))

__device__ __forceinline__ void mma16816(float* d, const unsigned* a, const unsigned* b){
  asm volatile("mma.sync.aligned.m16n8k16.row.col.f32.bf16.bf16.f32 "
    "{%0,%1,%2,%3},{%4,%5,%6,%7},{%8,%9},{%0,%1,%2,%3};"
    : "+f"(d[0]),"+f"(d[1]),"+f"(d[2]),"+f"(d[3])
    : "r"(a[0]),"r"(a[1]),"r"(a[2]),"r"(a[3]),"r"(b[0]),"r"(b[1]));
}
__device__ __forceinline__ void ldsm4(unsigned* r, unsigned addr){
  asm volatile("ldmatrix.sync.aligned.m8n8.x4.shared.b16 {%0,%1,%2,%3}, [%4];"
    : "=r"(r[0]),"=r"(r[1]),"=r"(r[2]),"=r"(r[3]) : "r"(addr));
}
__device__ __forceinline__ void ldsm4t(unsigned* r, unsigned addr){
  asm volatile("ldmatrix.sync.aligned.m8n8.x4.trans.shared.b16 {%0,%1,%2,%3}, [%4];"
    : "=r"(r[0]),"=r"(r[1]),"=r"(r[2]),"=r"(r[3]) : "r"(addr));
}

// ---------------------------------------------------------------------------
// Weight split-converts
// ---------------------------------------------------------------------------
__global__ void convsplit_kernel(const float* __restrict__ W,
                                 __nv_bfloat16* __restrict__ Wh,
                                 __nv_bfloat16* __restrict__ Wl,
                                 int Kk, int KPp, int total)
{
  int i = blockIdx.x*256 + threadIdx.x;
  if(i >= total) return;
  int r = i / Kk, c = i - r*Kk;
  float x = W[i];
  __nv_bfloat16 h = __float2bfloat16(x);
  Wh[(size_t)r*KPp + c] = h;
  Wl[(size_t)r*KPp + c] = __float2bfloat16(x - __bfloat162float(h));
}

__global__ void convsplit_qkv_kernel(const float* __restrict__ Wq,
                                     const float* __restrict__ Wk,
                                     const float* __restrict__ Wv,
                                     __nv_bfloat16* __restrict__ Wh,
                                     __nv_bfloat16* __restrict__ Wl)
{
  int i = blockIdx.x*256 + threadIdx.x;
  if(i >= 3*D*DH) return;
  int r = i / DH, c = i - r*DH;
  const float* src = (r < D) ? Wq : ((r < 2*D) ? Wk : Wv);
  int rl = (r < D) ? r : ((r < 2*D) ? r - D : r - 2*D);
  float x = src[(size_t)rl*DH + c];
  __nv_bfloat16 h = __float2bfloat16(x);
  Wh[(size_t)r*KP1 + c] = h;
  Wl[(size_t)r*KP1 + c] = __float2bfloat16(x - __bfloat162float(h));
}

// ---------------------------------------------------------------------------
// LayerNorm (+optional add) + add_time -> split planes
// ---------------------------------------------------------------------------
__global__ void ln_addtime_kernel(const float* __restrict__ in1, int ld1, int off1,
                                  const float* __restrict__ in2, int ld2, int off2,
                                  const float* __restrict__ gv, const float* __restrict__ bv,
                                  __nv_bfloat16* __restrict__ outh,
                                  __nv_bfloat16* __restrict__ outl,
                                  float* __restrict__ rawOut)
{
  __shared__ float red[8];
  int row = blockIdx.x, tid = threadIdx.x;
  float v[3];
  #pragma unroll
  for(int q=0;q<3;q++){
    int j = tid + q*256;
    float x = in1[(size_t)row*ld1 + off1 + j];
    if(in2) x += in2[(size_t)row*ld2 + off2 + j];
    v[q] = x;
    if(rawOut) rawOut[(size_t)row*D + j] = x;
  }
  float s  = v[0]+v[1]+v[2];
  float s2 = v[0]*v[0]+v[1]*v[1]+v[2]*v[2];
  s  = blockSum(s,  red);
  float mu = s * (1.f/768.f);
  s2 = blockSum(s2, red);
  float var = s2*(1.f/768.f) - mu*mu;
  float rstd = rsqrtf(var + 1e-5f);
  float w[3]; float n2 = 0.f;
  #pragma unroll
  for(int q=0;q<3;q++){
    int j = tid + q*256;
    w[q] = (v[q]-mu)*rstd*gv[j] + bv[j];
    n2 += w[q]*w[q];
  }
  n2 = blockSum(n2, red);
  #pragma unroll
  for(int q=0;q<3;q++){
    int j = tid + q*256;
    splitStore(outh + (size_t)row*KP1 + 1 + j, outl + (size_t)row*KP1 + 1 + j, w[q]);
  }
  if(tid==0) splitStore(outh + (size_t)row*KP1, outl + (size_t)row*KP1, sqrtf(1.f + n2));
}

// ---------------------------------------------------------------------------
// Tensor-core split-bf16 GEMM (verified R7)
// ---------------------------------------------------------------------------
#define HG_STAGE_BF16 20480
#define HG_STAGE_BYTES 40960
#define HG_SMEM_BYTES (3*HG_STAGE_BYTES)

__global__ void __launch_bounds__(256,1) hgemm_kernel(
    const __nv_bfloat16* __restrict__ Ah, const __nv_bfloat16* __restrict__ Al,
    const __nv_bfloat16* __restrict__ Bh, const __nv_bfloat16* __restrict__ Bl,
    float* __restrict__ Cf, __nv_bfloat16* __restrict__ Ch, __nv_bfloat16* __restrict__ Cl,
    int KP, int ldc, int mode)
{
  extern __shared__ __nv_bfloat16 smb[];
  int tid = threadIdx.x;
  int lane = tid & 31, wid = tid >> 5;
  int wm = wid >> 2, wn = wid & 3;
  int g = lane >> 2, t = lane & 3;
  int row0 = blockIdx.y*128, col0 = blockIdx.x*128;

  float acc[4][4][4];
  #pragma unroll
  for(int mi=0;mi<4;mi++)
    #pragma unroll
    for(int ni=0;ni<4;ni++)
      #pragma unroll
      for(int e=0;e<4;e++) acc[mi][ni][e]=0.f;

  const int niter = KP >> 5;
  const unsigned smemU = (unsigned)__cvta_generic_to_shared(smb);

  const int aRow = wm*64 + (lane&7) + ((lane>>3)&1)*8;
  const int aCol = ((lane>>4)&1)*8;
  const unsigned aOffH = (unsigned)((aRow*40 + aCol)*2);
  const int bRow8 = lane & 7;
  const int bSel  = (lane >> 3) & 1;
  const unsigned bOff4 = (unsigned)(20480 + ((bRow8)*40 + bSel*8)*2 + ((lane & 16) ? 10240 : 0));

  int ldrow = tid >> 2, ldcc = (tid & 3)*8;
  int ldrow2 = (tid+256) >> 2, ldcc2 = ((tid+256) & 3)*8;

  #define LOAD_STAGE(stg, k0) do{                                             \
    __nv_bfloat16* s = smb + (stg)*HG_STAGE_BF16;                             \
    cpasync16(s +          ldrow*40 + ldcc,  Ah + (size_t)(row0+ldrow)*KP + (k0) + ldcc);  \
    cpasync16(s +  5120 +  ldrow*40 + ldcc,  Al + (size_t)(row0+ldrow)*KP + (k0) + ldcc);  \
    cpasync16(s + 10240 +  ldrow*40 + ldcc,  Bh + (size_t)(col0+ldrow)*KP + (k0) + ldcc);  \
    cpasync16(s + 15360 +  ldrow*40 + ldcc,  Bl + (size_t)(col0+ldrow)*KP + (k0) + ldcc);  \
    cpasync16(s +          ldrow2*40 + ldcc2, Ah + (size_t)(row0+ldrow2)*KP + (k0) + ldcc2);\
    cpasync16(s +  5120 +  ldrow2*40 + ldcc2, Al + (size_t)(row0+ldrow2)*KP + (k0) + ldcc2);\
    cpasync16(s + 10240 +  ldrow2*40 + ldcc2, Bh + (size_t)(col0+ldrow2)*KP + (k0) + ldcc2);\
    cpasync16(s + 15360 +  ldrow2*40 + ldcc2, Bl + (size_t)(col0+ldrow2)*KP + (k0) + ldcc2);\
    CP_COMMIT;                                                                \
  } while(0)

  LOAD_STAGE(0, 0);
  LOAD_STAGE(1, 32);

  for(int it=0; it<niter; it++){
    if(it == niter-1){ CP_WAIT(0); } else { CP_WAIT(1); }
    __syncthreads();
    if(it+2 < niter) LOAD_STAGE((it+2)%3, (it+2)<<5);

    const unsigned sb = smemU + (unsigned)((it%3)*HG_STAGE_BYTES);

    #pragma unroll
    for(int ks=0;ks<2;ks++){
      unsigned a_h[4][4], a_l[4][4];
      #pragma unroll
      for(int mi=0;mi<4;mi++){
        unsigned ad = sb + aOffH + (unsigned)(mi*1280 + ks*32);
        ldsm4(a_h[mi], ad);
        ldsm4(a_l[mi], ad + 10240);
      }
      unsigned bhl[4][4];
      #pragma unroll
      for(int ni=0;ni<4;ni++){
        unsigned bd = sb + bOff4 + (unsigned)(wn*2560 + ni*640 + ks*32);
        ldsm4(bhl[ni], bd);
      }
      #pragma unroll
      for(int mi=0;mi<4;mi++)
        #pragma unroll
        for(int ni=0;ni<4;ni++) mma16816(acc[mi][ni], a_h[mi], bhl[ni]);
      #pragma unroll
      for(int mi=0;mi<4;mi++)
        #pragma unroll
        for(int ni=0;ni<4;ni++) mma16816(acc[mi][ni], a_h[mi], bhl[ni]+2);
      #pragma unroll
      for(int mi=0;mi<4;mi++)
        #pragma unroll
        for(int ni=0;ni<4;ni++) mma16816(acc[mi][ni], a_l[mi], bhl[ni]);
    }
  }

  int mat = blockIdx.x / 6;
  int cmatBase = mat*768;
  #pragma unroll
  for(int mi=0;mi<4;mi++){
    int rb = row0 + wm*64 + mi*16 + g;
    #pragma unroll
    for(int ni=0;ni<4;ni++){
      int cb = col0 + wn*32 + ni*8 + 2*t;
      float* a = acc[mi][ni];
      #pragma unroll
      for(int e=0;e<4;e++){
        int r = rb + (e>=2 ? 8 : 0);
        int c = cb + (e&1);
        float v = a[e];
        if(mode==2){
          v = 0.5f*v*(1.f + erff(v*0.70710678118654752f));
          splitStore(Ch + (size_t)r*ldc + c, Cl + (size_t)r*ldc + c, v);
        } else if(mode==1){
          int b_ = r >> 10, ii = r & 1023;
          int cmat = c - cmatBase;
          int h = cmat >> 6, cc2 = cmat & 63;
          Cf[(size_t)mat*(BH*SEQ*HDIM) + (size_t)(((b_*HEADS+h)<<10) + ii)*HDIM + cc2] = v;
        } else {
          Cf[(size_t)r*ldc + c] = v;
        }
      }
    }
  }
}

// ---------------------------------------------------------------------------
// Prep: qt, kt, v->v_tan; Q,K single bf16 planes; V split planes.
// ---------------------------------------------------------------------------
__global__ void prep_kernel()
{
  int w = blockIdx.x*8 + (threadIdx.x>>5);
  int lane = threadIdx.x & 31;

  const float* q = g_QKVf + (size_t)w*HDIM;
  float qv[2]; float s = 0.f;
  #pragma unroll
  for(int e=0;e<2;e++){ qv[e] = q[lane+32*e]; s += qv[e]*qv[e]; }
  s = warpSum(s);
  if(lane==0) g_qt[w] = sqrtf(1.f + s);
  #pragma unroll
  for(int e=0;e<2;e++)
    g_Qsph[(size_t)w*HDIM + lane+32*e] = __float2bfloat16(qv[e]);

  const float* k = g_QKVf + (size_t)(BH*SEQ)*HDIM + (size_t)w*HDIM;
  float kv[2]; s = 0.f;
  #pragma unroll
  for(int e=0;e<2;e++){ kv[e] = k[lane+32*e]; s += kv[e]*kv[e]; }
  s = warpSum(s);
  if(lane==0) g_kt[w] = sqrtf(1.f + s);
  #pragma unroll
  for(int e=0;e<2;e++)
    g_Ksph[(size_t)w*HDIM + lane+32*e] = __float2bfloat16(kv[e]);

  const float* v = g_QKVf + (size_t)(2*BH*SEQ)*HDIM + (size_t)w*HDIM;
  float vv[2]; s = 0.f;
  #pragma unroll
  for(int e=0;e<2;e++){ vv[e] = v[lane+32*e]; s += vv[e]*vv[e]; }
  s = warpSum(s);
  float sn = sqrtf(s);
  float vt = sqrtf(1.f + s);
  float vc = fmaxf(vt, 1.0000001f);
  float dist = __logf(vc + sqrtf((vc-1.f)*(vc+1.f)));
  float scl = dist / fmaxf(sn, 1e-8f);
  #pragma unroll
  for(int e=0;e<2;e++)
    splitStore(g_Vsph + (size_t)w*HDIM + lane+32*e, g_Vspl + (size_t)w*HDIM + lane+32*e, vv[e]*scl);
}

// ---------------------------------------------------------------------------
// Tensor-core fused hyperbolic flash attention.
//   QK^T 1-term; P.V 2-term.  cp.async double-buffered K/V/kt stages,
//   ldmatrix fragment loads (V via .trans -> no manual transpose).
// ---------------------------------------------------------------------------
#define AT_STR   72
#define AT_PLANE (64*AT_STR)          // 4608 bf16 per plane
#define AT_STAGE (3*AT_PLANE)         // K | Vh | Vl
#define AT_SMEM_BYTES (2*AT_STAGE*2 + 2*64*4)   // stages + kt floats

__device__ __forceinline__ float attn_logit(float sv, float qt, float cq, float rsh,
                                            float Bq, float ktj, float lam, float tau,
                                            float spm){
  float rawc = fmaxf(qt*ktj - sv, 1.0f);
  bool selfp = rawc < 1.00001f;
  float c = selfp ? 2.f : rawc;
  float x = (c-1.f)*(c+1.f);
  float rs = rsqrtf(fmaxf(x, 1e-12f));
  float sh = x*rs;
  float dist = __logf(c + sh);
  float ck = fmaxf(ktj, 1.0000001f);
  float Z = (rawc*cq - ck)*rs*rsh;
  Z = selfp ? 1.f : fminf(fmaxf(Z, -1.f), 1.f);
  float pen = -lam*__logf(1.f + dist*dist);
  float ent = __logf(1.f + __expf(Bq + Z - 0.1f)) - spm;
  return pen - tau*ent;
}

__global__ void __launch_bounds__(256,1) attn_kernel(
    const float* __restrict__ alpha_raw,
    const float* __restrict__ tau_raw,
    const float* __restrict__ lambda_raw)
{
  extern __shared__ __nv_bfloat16 smA[];
  float* ktsBuf = (float*)(smA + 2*AT_STAGE);   // [2][64]

  const int bh = blockIdx.y;
  const int qrow0 = blockIdx.x*128;
  const int tid = threadIdx.x;
  const int lane = tid & 31, wid = tid >> 5;
  const int g = lane >> 2, t = lane & 3;
  const unsigned smemU = (unsigned)__cvta_generic_to_shared(smA);

  const float alpha = log1pf(expf(alpha_raw[0]));
  const float tau   = log1pf(expf(tau_raw[0]));
  const float lam   = log1pf(expf(lambda_raw[0]));
  const float spm   = log1pf(expf(-0.1f));

  // ---- stage Q into stage-0 area, extract fragments ----
  {
    const __nv_bfloat16* gQ = g_Qsph + ((size_t)bh*SEQ + qrow0)*HDIM;
    #pragma unroll
    for(int itn=0; itn<4; itn++){
      int ch = tid + itn*256;
      int r = ch >> 3, c0 = (ch & 7)*8;
      *(uint4*)(smA + r*AT_STR + c0) = *(const uint4*)(gQ + r*HDIM + c0);
    }
  }
  __syncthreads();

  unsigned qh[4][4];
  {
    const unsigned* pQ = (const unsigned*)smA;
    int rbase = wid*16 + g;
    #pragma unroll
    for(int ks=0; ks<4; ks++){
      int base = rbase*(AT_STR/2) + ks*8 + t;
      qh[ks][0]=pQ[base];               qh[ks][1]=pQ[base+8*(AT_STR/2)];
      qh[ks][2]=pQ[base+4];             qh[ks][3]=pQ[base+8*(AT_STR/2)+4];
    }
  }
  __syncthreads();

  // per-row scalars
  const int rowL = qrow0 + wid*16 + g;
  const int rowH = rowL + 8;
  float qtL = g_qt[bh*SEQ + rowL], qtH = g_qt[bh*SEQ + rowH];
  float cqL = fmaxf(qtL, 1.0000001f), cqH = fmaxf(qtH, 1.0000001f);
  float ctL = fminf(__logf(cqL + sqrtf((cqL-1.f)*(cqL+1.f))), 40.f);
  float ctH = fminf(__logf(cqH + sqrtf((cqH-1.f)*(cqH+1.f))), 40.f);
  float rshL = 1.f/sinhf(ctL), rshH = 1.f/sinhf(ctH);
  float BqL = alpha*ctL/(1.f + alpha*ctL);
  float BqH = alpha*ctH/(1.f + alpha*ctH);

  float accO[8][4];
  #pragma unroll
  for(int ni=0;ni<8;ni++)
    #pragma unroll
    for(int e=0;e<4;e++) accO[ni][e]=0.f;
  float lsumL = 0.f, lsumH = 0.f;

  const __nv_bfloat16* gKh = g_Ksph + (size_t)bh*SEQ*HDIM;
  const __nv_bfloat16* gVh = g_Vsph + (size_t)bh*SEQ*HDIM;
  const __nv_bfloat16* gVl = g_Vspl + (size_t)bh*SEQ*HDIM;
  const float* gkt = g_kt + bh*SEQ;

  // lane-derived ldmatrix address components
  const int kj = (lane&7) + ((lane>>4)&1)*8;       // K: row within 16-j block
  const int kd = ((lane>>3)&1)*8;                   // K: d offset within 16
  const int vj = (lane&7) + ((lane>>3)&1)*8;        // V: j within 16
  const int vc = ((lane>>4)&1)*8;                   // V: col offset within 16

  // stage loader: 3 planes x 512 chunks = 1536 + 16 kt chunks
  #define AT_LOAD(stg, jb) do{                                                  \
    __nv_bfloat16* s = smA + (stg)*AT_STAGE;                                    \
    _Pragma("unroll")                                                           \
    for(int q_=0;q_<6;q_++){                                                    \
      int ch = tid + q_*256;                                                    \
      int pl = ch >> 9, cw = ch & 511;                                          \
      int r_ = cw >> 3, c_ = (cw & 7)*8;                                        \
      const __nv_bfloat16* src = (pl==0? gKh : (pl==1? gVh : gVl));             \
      cpasync16(s + pl*AT_PLANE + r_*AT_STR + c_,                               \
                src + (size_t)((jb)+r_)*HDIM + c_);                             \
    }                                                                           \
    if(tid < 16) cpasync16(ktsBuf + (stg)*64 + tid*4, gkt + (jb) + tid*4);      \
    CP_COMMIT;                                                                  \
  } while(0)

  AT_LOAD(0, 0);

  for(int jt=0; jt<16; jt++){
    if(jt+1 < 16){ AT_LOAD((jt+1)&1, (jt+1)*64); CP_WAIT(1); }
    else         { CP_WAIT(0); }
    __syncthreads();

    const unsigned sbK = smemU + (unsigned)(((jt&1)*AT_STAGE)*2);
    const unsigned sbVh = sbK + (unsigned)(AT_PLANE*2);
    const unsigned sbVl = sbK + (unsigned)(2*AT_PLANE*2);
    const float* kts = ktsBuf + (jt&1)*64;
    const int jbase = jt*64;

    // ---- S = Q.K^T (1-term), K frags via ldsm4 ----
    float accS[8][4];
    #pragma unroll
    for(int ni=0;ni<8;ni++)
      #pragma unroll
      for(int e=0;e<4;e++) accS[ni][e]=0.f;

    #pragma unroll
    for(int ks=0; ks<4; ks++){
      #pragma unroll
      for(int np=0; np<4; np++){
        unsigned kb[4];
        unsigned ad = sbK + (unsigned)(((np*16 + kj)*AT_STR + ks*16 + kd)*2);
        ldsm4(kb, ad);
        mma16816(accS[2*np],   qh[ks], kb);
        mma16816(accS[2*np+1], qh[ks], kb+2);
      }
    }

    // ---- logits + exp ----
    #pragma unroll
    for(int ni=0; ni<8; ni++){
      float2 ktp = *(const float2*)&kts[ni*8 + 2*t];
      float z0 = attn_logit(accS[ni][0], qtL, cqL, rshL, BqL, ktp.x, lam, tau, spm);
      float z1 = attn_logit(accS[ni][1], qtL, cqL, rshL, BqL, ktp.y, lam, tau, spm);
      float z2 = attn_logit(accS[ni][2], qtH, cqH, rshH, BqH, ktp.x, lam, tau, spm);
      float z3 = attn_logit(accS[ni][3], qtH, cqH, rshH, BqH, ktp.y, lam, tau, spm);
      float p0 = __expf(z0), p1 = __expf(z1), p2 = __expf(z2), p3 = __expf(z3);
      lsumL += p0 + p1;
      lsumH += p2 + p3;
      accS[ni][0]=p0; accS[ni][1]=p1; accS[ni][2]=p2; accS[ni][3]=p3;
    }

    // ---- O += P.V (2-term), V frags via ldsm4.trans ----
    #pragma unroll
    for(int kc=0; kc<4; kc++){
      unsigned aP[4];
      packhi(accS[2*kc  ][0], accS[2*kc  ][1], aP[0]);
      packhi(accS[2*kc  ][2], accS[2*kc  ][3], aP[1]);
      packhi(accS[2*kc+1][0], accS[2*kc+1][1], aP[2]);
      packhi(accS[2*kc+1][2], accS[2*kc+1][3], aP[3]);
      #pragma unroll
      for(int nq=0; nq<4; nq++){
        unsigned voff = (unsigned)(((kc*16 + vj)*AT_STR + nq*16 + vc)*2);
        unsigned vb[4], vlb[4];
        ldsm4t(vb,  sbVh + voff);
        ldsm4t(vlb, sbVl + voff);
        mma16816(accO[2*nq],   aP, vb);
        mma16816(accO[2*nq+1], aP, vb+2);
        mma16816(accO[2*nq],   aP, vlb);
        mma16816(accO[2*nq+1], aP, vlb+2);
      }
    }
    __syncthreads();
  }

  // ---- epilogue ----
  float lL = lsumL, lH = lsumH;
  #pragma unroll
  for(int o=1;o<4;o<<=1){
    lL += __shfl_xor_sync(0xffffffffu, lL, o);
    lH += __shfl_xor_sync(0xffffffffu, lH, o);
  }
  float invL = 1.f/(lL*(1.f + 1e-8f));
  float invH = 1.f/(lH*(1.f + 1e-8f));

  float agL[8][2], agH[8][2];
  float nnL = 0.f, nnH = 0.f;
  #pragma unroll
  for(int ni=0;ni<8;ni++){
    agL[ni][0] = accO[ni][0]*invL; agL[ni][1] = accO[ni][1]*invL;
    agH[ni][0] = accO[ni][2]*invH; agH[ni][1] = accO[ni][3]*invH;
    nnL += agL[ni][0]*agL[ni][0] + agL[ni][1]*agL[ni][1];
    nnH += agH[ni][0]*agH[ni][0] + agH[ni][1]*agH[ni][1];
  }
  #pragma unroll
  for(int o=1;o<4;o<<=1){
    nnL += __shfl_xor_sync(0xffffffffu, nnL, o);
    nnH += __shfl_xor_sync(0xffffffffu, nnH, o);
  }
  nnL = sqrtf(nnL); nnH = sqrtf(nnH);
  float tL = coshf(nnL), tH = coshf(nnH);
  float sclL = sinhf(nnL)/fmaxf(nnL, 1e-8f);
  float sclH = sinhf(nnH)/fmaxf(nnH, 1e-8f);

  const int b_ = bh / HEADS, h = bh % HEADS;
  const int growL = b_*SEQ + rowL, growH = b_*SEQ + rowH;
  #pragma unroll
  for(int ni=0;ni<8;ni++){
    int c0 = ni*8 + 2*t;
    size_t iL = (size_t)growL*KP1 + 1 + h*HDIM + c0;
    size_t iH = (size_t)growH*KP1 + 1 + h*HDIM + c0;
    splitStore(g_AINh + iL,     g_AINl + iL,     agL[ni][0]*sclL);
    splitStore(g_AINh + iL + 1, g_AINl + iL + 1, agL[ni][1]*sclL);
    splitStore(g_AINh + iH,     g_AINl + iH,     agH[ni][0]*sclH);
    splitStore(g_AINh + iH + 1, g_AINl + iH + 1, agH[ni][1]*sclH);
  }
  if(t==0){
    g_Th[growL*HEADS + h] = tL;
    g_Th[growH*HEADS + h] = tH;
  }
}

// t_new
__global__ void tnew_kernel()
{
  int r = blockIdx.x*256 + threadIdx.x;
  if(r >= ROWS) return;
  float s = 0.f;
  #pragma unroll
  for(int h=0; h<HEADS; h++){ float t = g_Th[r*HEADS+h]; s += t*t; }
  splitStore(g_AINh + (size_t)r*KP1, g_AINl + (size_t)r*KP1, sqrtf(s - (float)(HEADS-1)));
}

// time col for mlp hidden
__global__ void time_mlp_kernel()
{
  __shared__ float red[8];
  int row = blockIdx.x, tid = threadIdx.x;
  float s = 0.f;
  #pragma unroll
  for(int q=0;q<12;q++){
    size_t idx = (size_t)row*KP2 + 1 + tid + q*256;
    float x = __bfloat162float(g_H1h[idx]) + __bfloat162float(g_H1l[idx]);
    s += x*x;
  }
  s = blockSum(s, red);
  if(tid==0) splitStore(g_H1h + (size_t)row*KP2, g_H1l + (size_t)row*KP2, sqrtf(1.f + s));
}

// final
__global__ void final_kernel(float* __restrict__ out)
{
  __shared__ float red[8];
  int row = blockIdx.x, tid = threadIdx.x;
  float v[3]; float s = 0.f;
  #pragma unroll
  for(int q=0;q<3;q++){
    int j = tid + q*256;
    float x = g_G2[(size_t)row*D + j] + g_OUT[(size_t)row*D + j];
    v[q] = x; s += x*x;
  }
  s = blockSum(s, red);
  #pragma unroll
  for(int q=0;q<3;q++){
    int j = tid + q*256;
    out[(size_t)row*DH + 1 + j] = v[q];
  }
  if(tid==0) out[(size_t)row*DH] = sqrtf(1.f + s);
}

// ---------------------------------------------------------------------------
// Launch (ordered so attn_kernel is launch #5 for ncu -s 5)
// ---------------------------------------------------------------------------
extern "C" void kernel_launch(void* const* d_in, const int* in_sizes, int n_in,
                              void* d_out, int out_size)
{
  const float* x    = (const float*)d_in[0];
  const float* Wq   = (const float*)d_in[1];
  const float* Wk   = (const float*)d_in[2];
  const float* Wv   = (const float*)d_in[3];
  const float* Wo   = (const float*)d_in[4];
  const float* ln1g = (const float*)d_in[5];
  const float* ln1b = (const float*)d_in[6];
  const float* ln2g = (const float*)d_in[7];
  const float* ln2b = (const float*)d_in[8];
  const float* Wm1  = (const float*)d_in[9];
  const float* Wm2  = (const float*)d_in[10];
  const float* araw = (const float*)d_in[11];
  const float* traw = (const float*)d_in[12];
  const float* lraw = (const float*)d_in[13];
  float* out = (float*)d_out;

  float *pQKV, *pMO, *pOUT, *pG2;
  cudaGetSymbolAddress((void**)&pQKV, g_QKVf);
  cudaGetSymbolAddress((void**)&pMO,  g_MO);
  cudaGetSymbolAddress((void**)&pOUT, g_OUT);
  cudaGetSymbolAddress((void**)&pG2,  g_G2);

  __nv_bfloat16 *pX1h,*pX1l,*pAINh,*pAINl,*pHh,*pHl,*pH1h,*pH1l;
  __nv_bfloat16 *pWqkvh,*pWqkvl,*pWoh,*pWol,*pW1h,*pW1l,*pW2h,*pW2l;
  cudaGetSymbolAddress((void**)&pX1h,  g_X1h);  cudaGetSymbolAddress((void**)&pX1l,  g_X1l);
  cudaGetSymbolAddress((void**)&pAINh, g_AINh); cudaGetSymbolAddress((void**)&pAINl, g_AINl);
  cudaGetSymbolAddress((void**)&pHh,   g_Hh);   cudaGetSymbolAddress((void**)&pHl,   g_Hl);
  cudaGetSymbolAddress((void**)&pH1h,  g_H1h);  cudaGetSymbolAddress((void**)&pH1l,  g_H1l);
  cudaGetSymbolAddress((void**)&pWqkvh,g_Wqkvh);cudaGetSymbolAddress((void**)&pWqkvl,g_Wqkvl);
  cudaGetSymbolAddress((void**)&pWoh,  g_Woh);  cudaGetSymbolAddress((void**)&pWol,  g_Wol);
  cudaGetSymbolAddress((void**)&pW1h,  g_W1h);  cudaGetSymbolAddress((void**)&pW1l,  g_W1l);
  cudaGetSymbolAddress((void**)&pW2h,  g_W2h);  cudaGetSymbolAddress((void**)&pW2l,  g_W2l);

  cudaFuncSetAttribute(hgemm_kernel, cudaFuncAttributeMaxDynamicSharedMemorySize,
                       HG_SMEM_BYTES);
  cudaFuncSetAttribute(attn_kernel, cudaFuncAttributeMaxDynamicSharedMemorySize,
                       AT_SMEM_BYTES);

  // 0,1: weight converts needed before QKV/Wo GEMMs
  {
    int tq = 3*D*DH;
    convsplit_qkv_kernel<<<(tq+255)/256,256>>>(Wq, Wk, Wv, pWqkvh, pWqkvl);
    int t1 = D*DH;
    convsplit_kernel<<<(t1+255)/256,256>>>(Wo, pWoh, pWol, DH, KP1, t1);
  }

  // 2: ln1 + add_time
  ln_addtime_kernel<<<ROWS,256>>>(x, DH, 1, nullptr, 0, 0, ln1g, ln1b, pX1h, pX1l, nullptr);

  // 3: fused QKV projection
  dim3 gqkv(2304/128, ROWS/128);
  hgemm_kernel<<<gqkv,256,HG_SMEM_BYTES>>>(pX1h,pX1l, pWqkvh,pWqkvl, pQKV,nullptr,nullptr, KP1, 0, 1);

  // 4: prep
  prep_kernel<<<(BH*SEQ)/8, 256>>>();

  // 5: fused attention (profiled launch)
  attn_kernel<<<dim3(SEQ/128, BH), 256, AT_SMEM_BYTES>>>(araw, traw, lraw);

  // 6: t_new
  tnew_kernel<<<ROWS/256, 256>>>();

  // 7: Wm1 convert (deferred)
  {
    int t2 = DM*DH;
    convsplit_kernel<<<(t2+255)/256,256>>>(Wm1, pW1h, pW1l, DH, KP1, t2);
  }

  // 8: Wo projection
  dim3 g768(D/128, ROWS/128);
  hgemm_kernel<<<g768,256,HG_SMEM_BYTES>>>(pAINh,pAINl, pWoh,pWol, pMO,nullptr,nullptr, KP1, D, 0);

  // 9: residual + ln2
  ln_addtime_kernel<<<ROWS,256>>>(pMO, D, 0, x, DH, 1, ln2g, ln2b, pHh, pHl, pOUT);

  // 10: MLP up with gelu
  dim3 g3072(DM/128, ROWS/128);
  hgemm_kernel<<<g3072,256,HG_SMEM_BYTES>>>(pHh,pHl, pW1h,pW1l, nullptr, pH1h+1, pH1l+1, KP1, KP2, 2);

  // 11: Wm2 convert (deferred)
  {
    int t3 = D*DMH;
    convsplit_kernel<<<(t3+255)/256,256>>>(Wm2, pW2h, pW2l, DMH, KP2, t3);
  }

  // 12: mlp hidden time col
  time_mlp_kernel<<<ROWS,256>>>();

  // 13: MLP down
  hgemm_kernel<<<g768,256,HG_SMEM_BYTES>>>(pH1h,pH1l, pW2h,pW2l, pG2,nullptr,nullptr, KP2, D, 0);

  // 14: final
  final_kernel<<<ROWS,256>>>(out);
}